// round 13
// baseline (speedup 1.0000x reference)
#include <cuda_runtime.h>
#include <cstddef>
#include <cstdint>

// Problem constants
#define BB 8
#define TT 2048
#define DD 1024
#define HH 8
#define NN 32
#define MROWS (BB*TT)          // 16384
#define HN (HH*NN)             // 256

// ---------------------------------------------------------------------------
// Scratch (no cudaMalloc allowed) — __device__ globals.
// Split planes: packed bf16 pairs (one u32 = 2 bf16 along K).
// ---------------------------------------------------------------------------
__device__ unsigned g_xh [(size_t)MROWS * DD / 2];
__device__ unsigned g_xl [(size_t)MROWS * DD / 2];
__device__ unsigned g_xph[(size_t)MROWS * DD / 2];
__device__ unsigned g_xpl[(size_t)MROWS * DD / 2];
__device__ unsigned g_wih[(size_t)DD * DD / 2];
__device__ unsigned g_wil[(size_t)DD * DD / 2];
__device__ unsigned g_wkh[(size_t)HN * DD / 2];
__device__ unsigned g_wkl[(size_t)HN * DD / 2];
__device__ unsigned g_wvh[(size_t)HN * DD / 2];
__device__ unsigned g_wvl[(size_t)HN * DD / 2];
__device__ unsigned g_wqh[(size_t)HN * DD / 2];
__device__ unsigned g_wql[(size_t)HN * DD / 2];
__device__ unsigned g_wbh[(size_t)HN * DD / 2];
__device__ unsigned g_wbl[(size_t)HN * DD / 2];
__device__ unsigned g_woh[(size_t)DD * HN / 2];
__device__ unsigned g_wol[(size_t)DD * HN / 2];
__device__ float    g_k   [(size_t)MROWS * HN];
__device__ float    g_v   [(size_t)MROWS * HN];
__device__ float    g_q   [(size_t)MROWS * HN];
__device__ float    g_beta[(size_t)MROWS * HN];
__device__ unsigned short g_cellh[(size_t)MROWS * HN];
__device__ unsigned short g_celll[(size_t)MROWS * HN];

// ---------------------------------------------------------------------------
// bf16 split helpers
// ---------------------------------------------------------------------------
__device__ __forceinline__ float trunc_hi(float x) {
    return __uint_as_float(__float_as_uint(x) & 0xFFFF0000u);
}
__device__ __forceinline__ unsigned pack_hi_pair(float e0, float e1) {
    return __byte_perm(__float_as_uint(e0), __float_as_uint(e1), 0x7632);
}
__device__ __forceinline__ unsigned pack_lo_pair(float l0, float l1) {
    unsigned d;
    asm("cvt.rn.bf16x2.f32 %0, %1, %2;" : "=r"(d) : "f"(l1), "f"(l0));
    return d;
}

__global__ void __launch_bounds__(256)
split_kernel(const float2* __restrict__ in, unsigned* __restrict__ hi,
             unsigned* __restrict__ lo, int n)
{
    const int i = blockIdx.x * 256 + threadIdx.x;
    if (i < n) {
        const float2 v = in[i];
        hi[i] = pack_hi_pair(v.x, v.y);
        lo[i] = pack_lo_pair(v.x - trunc_hi(v.x), v.y - trunc_hi(v.y));
    }
}

__device__ __forceinline__ void mma_bf16(float d[4],
                                         unsigned a0, unsigned a1,
                                         unsigned a2, unsigned a3,
                                         unsigned b0, unsigned b1) {
    asm("mma.sync.aligned.m16n8k16.row.col.f32.bf16.bf16.f32 "
        "{%0,%1,%2,%3}, {%4,%5,%6,%7}, {%8,%9}, {%0,%1,%2,%3};"
        : "+f"(d[0]), "+f"(d[1]), "+f"(d[2]), "+f"(d[3])
        : "r"(a0), "r"(a1), "r"(a2), "r"(a3), "r"(b0), "r"(b1));
}

__device__ __forceinline__ void ldsm4(unsigned& r0, unsigned& r1,
                                      unsigned& r2, unsigned& r3, unsigned addr) {
    asm volatile("ldmatrix.sync.aligned.m8n8.x4.shared.b16 {%0,%1,%2,%3}, [%4];"
                 : "=r"(r0), "=r"(r1), "=r"(r2), "=r"(r3) : "r"(addr));
}

// ---------------------------------------------------------------------------
// bf16x2-compensated tensor GEMM on pre-split operands.
// C = epi( A @ W^T ). Block tile 128(M) x 128(N), chunk k16 (8 u32 words),
// 4 warps as 2M x 2N -> warp tile 64x64. 128 threads, 2 CTAs/SM.
// Per chunk per warp: 16 ldmatrix.x4 + 96 HMMA (1.33x less smem traffic
// per HMMA than the 64x32 layout, at healthy occupancy).
// epi: 0 identity(f32), 2 sigmoid(acc+bias), 3 head-band row-norm,
//      4 silu + split-write
// ---------------------------------------------------------------------------
#define PLW 12
#define APLANE (128 * PLW)          // u32 per plane (A and W identical)
#define BUFW (4 * APLANE)           // 4 planes per stage buffer (6144 u32)
#define SMEM_GB (2 * BUFW * 4)      // 49152 bytes

__device__ __forceinline__ void mma_gemm_core(
    const unsigned* __restrict__ Ah, const unsigned* __restrict__ Al,
    const unsigned* __restrict__ Wh, const unsigned* __restrict__ Wl,
    float* __restrict__ C, unsigned* __restrict__ Chi, unsigned* __restrict__ Clo,
    const float* __restrict__ bias,
    int epi, int Nout, int Kw, int row0, int col0)
{
    extern __shared__ unsigned sm[];   // [2][BUFW]

    const int tid  = threadIdx.x;
    const int wid  = tid >> 5;
    const int lane = tid & 31;
    const int g    = lane >> 2;
    const int c    = lane & 3;
    const int wm   = (wid & 1) * 64;   // warp M offset (0 or 64)
    const int wn   = (wid >> 1) * 64;  // warp N offset (0 or 64)

    // staging: thread covers A row tid (8 words) and W row tid (8 words)
    const unsigned* ApH = Ah + (size_t)(row0 + tid) * Kw;
    const unsigned* ApL = Al + (size_t)(row0 + tid) * Kw;
    const unsigned* WpH = Wh + (size_t)(col0 + tid) * Kw;
    const unsigned* WpL = Wl + (size_t)(col0 + tid) * Kw;
    const int sa = tid * PLW;

    const unsigned smb = (unsigned)__cvta_generic_to_shared(&sm[0]);
    const unsigned aoff = (((lane & 15) * PLW) + ((lane >> 4) << 2)) * 4;
    const unsigned boff = ((((lane >> 4) * 8 + (lane & 7)) * PLW) + ((lane & 8) ? 4 : 0)) * 4;

    float acc[4][8][4];
#pragma unroll
    for (int mt = 0; mt < 4; ++mt)
#pragma unroll
        for (int nt = 0; nt < 8; ++nt)
#pragma unroll
            for (int e = 0; e < 4; ++e) acc[mt][nt][e] = 0.f;

    const int nchunks = Kw / 8;

    // prologue: stage chunk 0 into buffer 0
    {
        *reinterpret_cast<uint4*>(&sm[0 * APLANE + sa])     = *reinterpret_cast<const uint4*>(ApH);
        *reinterpret_cast<uint4*>(&sm[0 * APLANE + sa + 4]) = *reinterpret_cast<const uint4*>(ApH + 4);
        *reinterpret_cast<uint4*>(&sm[1 * APLANE + sa])     = *reinterpret_cast<const uint4*>(ApL);
        *reinterpret_cast<uint4*>(&sm[1 * APLANE + sa + 4]) = *reinterpret_cast<const uint4*>(ApL + 4);
        *reinterpret_cast<uint4*>(&sm[2 * APLANE + sa])     = *reinterpret_cast<const uint4*>(WpH);
        *reinterpret_cast<uint4*>(&sm[2 * APLANE + sa + 4]) = *reinterpret_cast<const uint4*>(WpH + 4);
        *reinterpret_cast<uint4*>(&sm[3 * APLANE + sa])     = *reinterpret_cast<const uint4*>(WpL);
        *reinterpret_cast<uint4*>(&sm[3 * APLANE + sa + 4]) = *reinterpret_cast<const uint4*>(WpL + 4);
    }
    __syncthreads();

    for (int chunk = 0; chunk < nchunks; ++chunk) {
        const int cur = chunk & 1;
        const bool more = (chunk + 1 < nchunks);

        uint4 fa0, fa1, fl0, fl1, fw0, fw1, fx0, fx1;
        if (more) {
            const int ko = (chunk + 1) * 8;
            fa0 = *reinterpret_cast<const uint4*>(ApH + ko);
            fa1 = *reinterpret_cast<const uint4*>(ApH + ko + 4);
            fl0 = *reinterpret_cast<const uint4*>(ApL + ko);
            fl1 = *reinterpret_cast<const uint4*>(ApL + ko + 4);
            fw0 = *reinterpret_cast<const uint4*>(WpH + ko);
            fw1 = *reinterpret_cast<const uint4*>(WpH + ko + 4);
            fx0 = *reinterpret_cast<const uint4*>(WpL + ko);
            fx1 = *reinterpret_cast<const uint4*>(WpL + ko + 4);
        }

        const unsigned pb = smb + (unsigned)cur * (BUFW * 4);

        // B fragments: 4 nt-pairs x (hi, lo)  (warp N band = 64 cols)
        unsigned bh[4][4], bl[4][4];
#pragma unroll
        for (int pr = 0; pr < 4; ++pr) {
            const unsigned ba = pb + (2 * APLANE) * 4 + (unsigned)(wn + pr * 16) * PLW * 4 + boff;
            ldsm4(bh[pr][0], bh[pr][1], bh[pr][2], bh[pr][3], ba);
            ldsm4(bl[pr][0], bl[pr][1], bl[pr][2], bl[pr][3], ba + APLANE * 4);
        }

#pragma unroll
        for (int mt = 0; mt < 4; ++mt) {
            unsigned ah[4], al[4];
            const unsigned aa = pb + (unsigned)(wm + mt * 16) * PLW * 4 + aoff;
            ldsm4(ah[0], ah[1], ah[2], ah[3], aa);
            ldsm4(al[0], al[1], al[2], al[3], aa + APLANE * 4);
#pragma unroll
            for (int nt = 0; nt < 8; ++nt) {
                const unsigned b0 = bh[nt >> 1][(nt & 1) * 2];
                const unsigned b1 = bh[nt >> 1][(nt & 1) * 2 + 1];
                const unsigned c0 = bl[nt >> 1][(nt & 1) * 2];
                const unsigned c1 = bl[nt >> 1][(nt & 1) * 2 + 1];
                float* d = acc[mt][nt];
                mma_bf16(d, ah[0], ah[1], ah[2], ah[3], b0, b1); // hh
                mma_bf16(d, al[0], al[1], al[2], al[3], b0, b1); // lh
                mma_bf16(d, ah[0], ah[1], ah[2], ah[3], c0, c1); // hl
            }
        }

        if (more) {
            const int nxt = cur ^ 1;
            unsigned* sb = &sm[nxt * BUFW];
            *reinterpret_cast<uint4*>(&sb[0 * APLANE + sa])     = fa0;
            *reinterpret_cast<uint4*>(&sb[0 * APLANE + sa + 4]) = fa1;
            *reinterpret_cast<uint4*>(&sb[1 * APLANE + sa])     = fl0;
            *reinterpret_cast<uint4*>(&sb[1 * APLANE + sa + 4]) = fl1;
            *reinterpret_cast<uint4*>(&sb[2 * APLANE + sa])     = fw0;
            *reinterpret_cast<uint4*>(&sb[2 * APLANE + sa + 4]) = fw1;
            *reinterpret_cast<uint4*>(&sb[3 * APLANE + sa])     = fx0;
            *reinterpret_cast<uint4*>(&sb[3 * APLANE + sa + 4]) = fx1;
        }
        __syncthreads();
    }

    if (epi == 3) {
        // k-projection: per-row norm over each 32-col head band.
        // Warp band = 64 cols = 2 heads: nt 0..3 -> head 0, nt 4..7 -> head 1.
#pragma unroll
        for (int mt = 0; mt < 4; ++mt) {
            float sE[2] = {0.f, 0.f}, sO[2] = {0.f, 0.f};
#pragma unroll
            for (int nt = 0; nt < 8; ++nt) {
                const int hsel = nt >> 2;
                sE[hsel] = fmaf(acc[mt][nt][0], acc[mt][nt][0], sE[hsel]);
                sE[hsel] = fmaf(acc[mt][nt][1], acc[mt][nt][1], sE[hsel]);
                sO[hsel] = fmaf(acc[mt][nt][2], acc[mt][nt][2], sO[hsel]);
                sO[hsel] = fmaf(acc[mt][nt][3], acc[mt][nt][3], sO[hsel]);
            }
            float iE[2], iO[2];
#pragma unroll
            for (int h2 = 0; h2 < 2; ++h2) {
                float se = sE[h2], so = sO[h2];
                se += __shfl_xor_sync(0xffffffffu, se, 1);
                se += __shfl_xor_sync(0xffffffffu, se, 2);
                so += __shfl_xor_sync(0xffffffffu, so, 1);
                so += __shfl_xor_sync(0xffffffffu, so, 2);
                iE[h2] = __fdividef(1.f, sqrtf(se) + 1e-6f);
                iO[h2] = __fdividef(1.f, sqrtf(so) + 1e-6f);
            }
            const int r0 = row0 + wm + mt * 16 + g;
#pragma unroll
            for (int nt = 0; nt < 8; ++nt) {
                const int hsel = nt >> 2;
                const int cc = col0 + wn + nt * 8 + 2 * c;
                *reinterpret_cast<float2*>(C + (size_t)r0 * Nout + cc) =
                    make_float2(acc[mt][nt][0] * iE[hsel], acc[mt][nt][1] * iE[hsel]);
                *reinterpret_cast<float2*>(C + (size_t)(r0 + 8) * Nout + cc) =
                    make_float2(acc[mt][nt][2] * iO[hsel], acc[mt][nt][3] * iO[hsel]);
            }
        }
        return;
    }

#pragma unroll
    for (int mt = 0; mt < 4; ++mt) {
        const int r0 = row0 + wm + mt * 16 + g;
#pragma unroll
        for (int nt = 0; nt < 8; ++nt) {
            const int cc = col0 + wn + nt * 8 + 2 * c;
            float d0 = acc[mt][nt][0], d1 = acc[mt][nt][1];
            float d2 = acc[mt][nt][2], d3 = acc[mt][nt][3];
            if (epi == 4) {
                d0 = d0 * __fdividef(1.f, 1.f + __expf(-d0));
                d1 = d1 * __fdividef(1.f, 1.f + __expf(-d1));
                d2 = d2 * __fdividef(1.f, 1.f + __expf(-d2));
                d3 = d3 * __fdividef(1.f, 1.f + __expf(-d3));
                const size_t w0 = ((size_t)r0 * Nout + cc) >> 1;
                const size_t w1 = ((size_t)(r0 + 8) * Nout + cc) >> 1;
                Chi[w0] = pack_hi_pair(d0, d1);
                Clo[w0] = pack_lo_pair(d0 - trunc_hi(d0), d1 - trunc_hi(d1));
                Chi[w1] = pack_hi_pair(d2, d3);
                Clo[w1] = pack_lo_pair(d2 - trunc_hi(d2), d3 - trunc_hi(d3));
                continue;
            }
            if (epi == 2) {
                const float b0 = bias[cc], b1 = bias[cc + 1];
                d0 = __fdividef(1.f, 1.f + __expf(-(d0 + b0)));
                d1 = __fdividef(1.f, 1.f + __expf(-(d1 + b1)));
                d2 = __fdividef(1.f, 1.f + __expf(-(d2 + b0)));
                d3 = __fdividef(1.f, 1.f + __expf(-(d3 + b1)));
            }
            *reinterpret_cast<float2*>(C + (size_t)r0 * Nout + cc)       = make_float2(d0, d1);
            *reinterpret_cast<float2*>(C + (size_t)(r0 + 8) * Nout + cc) = make_float2(d2, d3);
        }
    }
}

template<int EPI>
__global__ void __launch_bounds__(128, 2)
gemm_bf16(const unsigned* __restrict__ Ah, const unsigned* __restrict__ Al,
          const unsigned* __restrict__ Wh, const unsigned* __restrict__ Wl,
          float* __restrict__ C, unsigned* __restrict__ Chi, unsigned* __restrict__ Clo,
          const float* __restrict__ bias, int Nout, int Kw)
{
    mma_gemm_core(Ah, Al, Wh, Wl, C, Chi, Clo, bias, EPI, Nout, Kw,
                  blockIdx.y * 128, blockIdx.x * 128);
}

struct ProjPtrs {
    const unsigned* Wh[4];
    const unsigned* Wl[4];
    float*          C[4];
};

// z: 0 = k (head-band normalize), 1 = v, 2 = q, 3 = beta (sigmoid+bias)
__global__ void __launch_bounds__(128, 2)
gemm_proj4(const unsigned* __restrict__ Ah, const unsigned* __restrict__ Al,
           ProjPtrs p, const float* __restrict__ bias, int Nout, int Kw)
{
    const int z = blockIdx.z;
    const int epi = (z == 0) ? 3 : ((z == 3) ? 2 : 0);
    mma_gemm_core(Ah, Al, p.Wh[z], p.Wl[z], p.C[z], nullptr, nullptr, bias,
                  epi, Nout, Kw, blockIdx.y * 128, blockIdx.x * 128);
}

// ---------------------------------------------------------------------------
// Barrier-free sequential scan (proven round-8/9 tiling: 2 cols/lane,
// 2 rows/warp, 16 warps/chain). Writes cell as split bf16 hi/lo planes.
// ---------------------------------------------------------------------------
#define PF 4

__global__ void __launch_bounds__(128)
scan_kernel(const float* __restrict__ Kn, const float* __restrict__ Vp,
            const float* __restrict__ Qp, const float* __restrict__ Bp,
            unsigned short* __restrict__ cellh, unsigned short* __restrict__ celll,
            float* __restrict__ S_final, int writeS)
{
    const int g     = blockIdx.x * 4 + (threadIdx.x >> 5);
    const int chain = g >> 4;
    const int wc    = g & 15;
    const int l     = threadIdx.x & 31;
    const int i     = wc * 2 + (l >> 4);
    const int j0    = (l & 15) * 2;
    const size_t cb = ((size_t)(chain >> 3) * TT) * HN + (size_t)(chain & 7) * NN;

    float2 pk[PF], pq[PF];
    float  pv[PF], pb[PF];
#pragma unroll
    for (int d = 0; d < PF; ++d) {
        const size_t a = cb + (size_t)d * HN;
        pk[d] = *reinterpret_cast<const float2*>(Kn + a + j0);
        pq[d] = *reinterpret_cast<const float2*>(Qp + a + j0);
        pv[d] = Vp[a + i];
        pb[d] = Bp[a + i];
    }

    float S0 = 0.f, S1 = 0.f, sqp = 0.f;
    size_t base = cb;

    for (int t = 0; t < TT; t += PF) {
#pragma unroll
        for (int u = 0; u < PF; ++u) {
            const int tcur = t + u;
            const int tpre = (tcur + PF < TT) ? (tcur + PF) : (TT - 1);
            const size_t pa = cb + (size_t)tpre * HN;
            const float2 nk = *reinterpret_cast<const float2*>(Kn + pa + j0);
            const float2 nq = *reinterpret_cast<const float2*>(Qp + pa + j0);
            const float  nv = Vp[pa + i];
            const float  nb = Bp[pa + i];

            const float k0 = pk[u].x, k1 = pk[u].y;

            float uu = fmaf(S1, k1, S0 * k0);
            float sv = sqp;
#pragma unroll
            for (int o = 1; o < 16; o <<= 1) {
                uu += __shfl_xor_sync(0xffffffffu, uu, o);
                sv += __shfl_xor_sync(0xffffffffu, sv, o);
            }
            if (tcur > 0 && (l & 15) == 0) {
                const float ov = sv * sv * __fdividef(1.f, 1.f + __expf(-sv));
                cellh[base - HN + i] = (unsigned short)(__float_as_uint(ov) >> 16);
                unsigned short lo16;
                const float res = ov - trunc_hi(ov);
                asm("cvt.rn.bf16.f32 %0, %1;" : "=h"(lo16) : "f"(res));
                celll[base - HN + i] = lo16;
            }

            const float delta = pv[u] - uu;
            const float bi    = pb[u];
            const float z0 = fmaf(bi, S0, delta * k0);
            const float z1 = fmaf(bi, S1, delta * k1);
            const float e0 = __expf(2.f * z0);
            const float e1 = __expf(2.f * z1);
            S0 = 1.f - __fdividef(2.f, e0 + 1.f);
            S1 = 1.f - __fdividef(2.f, e1 + 1.f);

            sqp = fmaf(S1, pq[u].y, S0 * pq[u].x);

            pk[u] = nk; pq[u] = nq; pv[u] = nv; pb[u] = nb;
            base += HN;
        }
    }

    float sv = sqp;
#pragma unroll
    for (int o = 1; o < 16; o <<= 1) sv += __shfl_xor_sync(0xffffffffu, sv, o);
    if ((l & 15) == 0) {
        const float ov = sv * sv * __fdividef(1.f, 1.f + __expf(-sv));
        cellh[base - HN + i] = (unsigned short)(__float_as_uint(ov) >> 16);
        unsigned short lo16;
        const float res = ov - trunc_hi(ov);
        asm("cvt.rn.bf16.f32 %0, %1;" : "=h"(lo16) : "f"(res));
        celll[base - HN + i] = lo16;
    }

    if (writeS) {
        S_final[((size_t)chain * NN + i) * NN + j0]     = S0;
        S_final[((size_t)chain * NN + i) * NN + j0 + 1] = S1;
    }
}

// ---------------------------------------------------------------------------
// Host launcher
// ---------------------------------------------------------------------------
extern "C" void kernel_launch(void* const* d_in, const int* in_sizes, int n_in,
                              void* d_out, int out_size)
{
    const float* x      = (const float*)d_in[0];
    const float* W_in   = (const float*)d_in[1];
    const float* W_k    = (const float*)d_in[2];
    const float* W_v    = (const float*)d_in[3];
    const float* W_q    = (const float*)d_in[4];
    const float* W_beta = (const float*)d_in[5];
    const float* b_beta = (const float*)d_in[6];
    const float* W_out  = (const float*)d_in[7];
    float* y = (float*)d_out;

    unsigned *xh, *xl, *xph, *xpl, *wih, *wil;
    unsigned *wkh, *wkl, *wvh, *wvl, *wqh, *wql, *wbh, *wbl, *woh, *wol;
    float *k, *v, *q, *bt;
    unsigned short *cellh, *celll;
    cudaGetSymbolAddress((void**)&xh,  g_xh);  cudaGetSymbolAddress((void**)&xl,  g_xl);
    cudaGetSymbolAddress((void**)&xph, g_xph); cudaGetSymbolAddress((void**)&xpl, g_xpl);
    cudaGetSymbolAddress((void**)&wih, g_wih); cudaGetSymbolAddress((void**)&wil, g_wil);
    cudaGetSymbolAddress((void**)&wkh, g_wkh); cudaGetSymbolAddress((void**)&wkl, g_wkl);
    cudaGetSymbolAddress((void**)&wvh, g_wvh); cudaGetSymbolAddress((void**)&wvl, g_wvl);
    cudaGetSymbolAddress((void**)&wqh, g_wqh); cudaGetSymbolAddress((void**)&wql, g_wql);
    cudaGetSymbolAddress((void**)&wbh, g_wbh); cudaGetSymbolAddress((void**)&wbl, g_wbl);
    cudaGetSymbolAddress((void**)&woh, g_woh); cudaGetSymbolAddress((void**)&wol, g_wol);
    cudaGetSymbolAddress((void**)&k,  g_k);  cudaGetSymbolAddress((void**)&v,  g_v);
    cudaGetSymbolAddress((void**)&q,  g_q);  cudaGetSymbolAddress((void**)&bt, g_beta);
    cudaGetSymbolAddress((void**)&cellh, g_cellh);
    cudaGetSymbolAddress((void**)&celll, g_celll);

    cudaFuncSetAttribute(gemm_bf16<0>, cudaFuncAttributeMaxDynamicSharedMemorySize, SMEM_GB);
    cudaFuncSetAttribute(gemm_bf16<4>, cudaFuncAttributeMaxDynamicSharedMemorySize, SMEM_GB);
    cudaFuncSetAttribute(gemm_proj4,   cudaFuncAttributeMaxDynamicSharedMemorySize, SMEM_GB);

    const int M = MROWS;

    // 0. split fp32 operands into bf16 hi/lo planes
    split_kernel<<<(M * DD / 2) / 256, 256>>>((const float2*)x, xh, xl, M * DD / 2);
    split_kernel<<<(DD * DD / 2) / 256, 256>>>((const float2*)W_in, wih, wil, DD * DD / 2);
    split_kernel<<<(HN * DD / 2) / 256, 256>>>((const float2*)W_k, wkh, wkl, HN * DD / 2);
    split_kernel<<<(HN * DD / 2) / 256, 256>>>((const float2*)W_v, wvh, wvl, HN * DD / 2);
    split_kernel<<<(HN * DD / 2) / 256, 256>>>((const float2*)W_q, wqh, wql, HN * DD / 2);
    split_kernel<<<(HN * DD / 2) / 256, 256>>>((const float2*)W_beta, wbh, wbl, HN * DD / 2);
    split_kernel<<<(DD * HN / 2) / 256, 256>>>((const float2*)W_out, woh, wol, DD * HN / 2);

    // 1. xp = silu(x @ W_in^T) -> split planes (epi 4)
    gemm_bf16<4><<<dim3(DD / 128, M / 128), 128, SMEM_GB>>>(
        xh, xl, wih, wil, nullptr, xph, xpl, nullptr, DD, DD / 2);

    // 2. fused projections: k (normalized), v, q, beta
    ProjPtrs p;
    p.Wh[0] = wkh; p.Wl[0] = wkl; p.C[0] = k;
    p.Wh[1] = wvh; p.Wl[1] = wvl; p.C[1] = v;
    p.Wh[2] = wqh; p.Wl[2] = wql; p.C[2] = q;
    p.Wh[3] = wbh; p.Wl[3] = wbl; p.C[3] = bt;
    gemm_proj4<<<dim3(HN / 128, M / 128, 4), 128, SMEM_GB>>>(
        xph, xpl, p, b_beta, HN, DD / 2);

    // 3. sequential scan (writes cell as split bf16 planes)
    const size_t y_elems = (size_t)M * DD;
    const int writeS = (out_size >= (int)(y_elems + (size_t)BB * HH * NN * NN)) ? 1 : 0;
    scan_kernel<<<256, 128>>>(k, v, q, bt, cellh, celll, y + y_elems, writeS);

    // 4. y = cell @ W_out^T
    gemm_bf16<0><<<dim3(DD / 128, M / 128), 128, SMEM_GB>>>(
        (const unsigned*)cellh, (const unsigned*)celll, woh, wol,
        y, nullptr, nullptr, nullptr, DD, HN / 2);
}

// round 14
// speedup vs baseline: 1.1982x; 1.1982x over previous
#include <cuda_runtime.h>
#include <cstddef>
#include <cstdint>

// Problem constants
#define BB 8
#define TT 2048
#define DD 1024
#define HH 8
#define NN 32
#define MROWS (BB*TT)          // 16384
#define HN (HH*NN)             // 256

// ---------------------------------------------------------------------------
// Scratch (no cudaMalloc allowed) — __device__ globals.
// Split planes: packed bf16 pairs (one u32 = 2 bf16 along K).
// ---------------------------------------------------------------------------
__device__ unsigned g_xh [(size_t)MROWS * DD / 2];
__device__ unsigned g_xl [(size_t)MROWS * DD / 2];
__device__ unsigned g_xph[(size_t)MROWS * DD / 2];
__device__ unsigned g_xpl[(size_t)MROWS * DD / 2];
__device__ unsigned g_wih[(size_t)DD * DD / 2];
__device__ unsigned g_wil[(size_t)DD * DD / 2];
__device__ unsigned g_wkh[(size_t)HN * DD / 2];
__device__ unsigned g_wkl[(size_t)HN * DD / 2];
__device__ unsigned g_wvh[(size_t)HN * DD / 2];
__device__ unsigned g_wvl[(size_t)HN * DD / 2];
__device__ unsigned g_wqh[(size_t)HN * DD / 2];
__device__ unsigned g_wql[(size_t)HN * DD / 2];
__device__ unsigned g_wbh[(size_t)HN * DD / 2];
__device__ unsigned g_wbl[(size_t)HN * DD / 2];
__device__ unsigned g_woh[(size_t)DD * HN / 2];
__device__ unsigned g_wol[(size_t)DD * HN / 2];
__device__ float    g_k   [(size_t)MROWS * HN];
__device__ float    g_v   [(size_t)MROWS * HN];
__device__ float    g_q   [(size_t)MROWS * HN];
__device__ float    g_beta[(size_t)MROWS * HN];
__device__ unsigned short g_cellh[(size_t)MROWS * HN];
__device__ unsigned short g_celll[(size_t)MROWS * HN];

// ---------------------------------------------------------------------------
// bf16 split helpers
// ---------------------------------------------------------------------------
__device__ __forceinline__ float trunc_hi(float x) {
    return __uint_as_float(__float_as_uint(x) & 0xFFFF0000u);
}
__device__ __forceinline__ unsigned pack_hi_pair(float e0, float e1) {
    return __byte_perm(__float_as_uint(e0), __float_as_uint(e1), 0x7632);
}
__device__ __forceinline__ unsigned pack_lo_pair(float l0, float l1) {
    unsigned d;
    asm("cvt.rn.bf16x2.f32 %0, %1, %2;" : "=r"(d) : "f"(l1), "f"(l0));
    return d;
}

__global__ void __launch_bounds__(256)
split_kernel(const float2* __restrict__ in, unsigned* __restrict__ hi,
             unsigned* __restrict__ lo, int n)
{
    const int i = blockIdx.x * 256 + threadIdx.x;
    if (i < n) {
        const float2 v = in[i];
        hi[i] = pack_hi_pair(v.x, v.y);
        lo[i] = pack_lo_pair(v.x - trunc_hi(v.x), v.y - trunc_hi(v.y));
    }
}

__device__ __forceinline__ void mma_bf16(float d[4],
                                         unsigned a0, unsigned a1,
                                         unsigned a2, unsigned a3,
                                         unsigned b0, unsigned b1) {
    asm("mma.sync.aligned.m16n8k16.row.col.f32.bf16.bf16.f32 "
        "{%0,%1,%2,%3}, {%4,%5,%6,%7}, {%8,%9}, {%0,%1,%2,%3};"
        : "+f"(d[0]), "+f"(d[1]), "+f"(d[2]), "+f"(d[3])
        : "r"(a0), "r"(a1), "r"(a2), "r"(a3), "r"(b0), "r"(b1));
}

__device__ __forceinline__ void ldsm4(unsigned& r0, unsigned& r1,
                                      unsigned& r2, unsigned& r3, unsigned addr) {
    asm volatile("ldmatrix.sync.aligned.m8n8.x4.shared.b16 {%0,%1,%2,%3}, [%4];"
                 : "=r"(r0), "=r"(r1), "=r"(r2), "=r"(r3) : "r"(addr));
}

// cp.async helpers (L2 -> smem, bypassing L1/register round trip)
__device__ __forceinline__ void cpa16(unsigned dst, const void* src) {
    asm volatile("cp.async.cg.shared.global [%0], [%1], 16;" :: "r"(dst), "l"(src));
}
__device__ __forceinline__ void cpa_commit() {
    asm volatile("cp.async.commit_group;" ::: "memory");
}
template<int N>
__device__ __forceinline__ void cpa_wait() {
    asm volatile("cp.async.wait_group %0;" :: "n"(N) : "memory");
}

// ---------------------------------------------------------------------------
// bf16x2-compensated tensor GEMM (round-9 proven 64x32 warp tile) with
// cp.async 3-stage pipeline.
// C = epi( A @ W^T ). Block 128x128, chunk k16 (8 u32 words), 8 warps 2Mx4N,
// 256 threads, 2 CTAs/SM. Per chunk per warp: 12 ldmatrix.x4 + 48 HMMA.
// epi: 0 identity(f32), 2 sigmoid(acc+bias), 3 head-band row-norm,
//      4 silu + split-write
// ---------------------------------------------------------------------------
#define PLW 12
#define PLANE (128 * PLW)           // u32 per plane (1536)
#define STAGEW (4 * PLANE)          // u32 per stage (6144)
#define NSTAGE 3
#define SMEM_GB (NSTAGE * STAGEW * 4)   // 73728 bytes

__device__ __forceinline__ void mma_gemm_core(
    const unsigned* __restrict__ Ah, const unsigned* __restrict__ Al,
    const unsigned* __restrict__ Wh, const unsigned* __restrict__ Wl,
    float* __restrict__ C, unsigned* __restrict__ Chi, unsigned* __restrict__ Clo,
    const float* __restrict__ bias,
    int epi, int Nout, int Kw, int row0, int col0)
{
    extern __shared__ unsigned sm[];   // [NSTAGE][STAGEW]

    const int tid  = threadIdx.x;
    const int wid  = tid >> 5;
    const int lane = tid & 31;
    const int g    = lane >> 2;
    const int c    = lane & 3;
    const int wm   = (wid & 1) * 64;
    const int wn   = (wid >> 1) * 32;

    // staging: thread covers row lr, word-half wsel (16B per plane per chunk)
    const int lr   = tid >> 1;
    const int wsel = tid & 1;
    const unsigned* Aph = Ah + (size_t)(row0 + lr) * Kw + wsel * 4;
    const unsigned* Apl = Al + (size_t)(row0 + lr) * Kw + wsel * 4;
    const unsigned* Wph = Wh + (size_t)(col0 + lr) * Kw + wsel * 4;
    const unsigned* Wpl = Wl + (size_t)(col0 + lr) * Kw + wsel * 4;
    const unsigned srow4 = (unsigned)(lr * PLW + wsel * 4) * 4;  // byte offset in plane

    const unsigned smb = (unsigned)__cvta_generic_to_shared(&sm[0]);
    const unsigned aoff = (((lane & 15) * PLW) + ((lane >> 4) << 2)) * 4;
    const unsigned boff = ((((lane >> 4) * 8 + (lane & 7)) * PLW) + ((lane & 8) ? 4 : 0)) * 4;

    float acc[4][4][4];
#pragma unroll
    for (int mt = 0; mt < 4; ++mt)
#pragma unroll
        for (int nt = 0; nt < 4; ++nt)
#pragma unroll
            for (int e = 0; e < 4; ++e) acc[mt][nt][e] = 0.f;

    const int nchunks = Kw / 8;

    // issue one chunk's copies into a stage (4 x 16B per thread) + commit
    auto issue = [&](int chunk, int stage) {
        const int ko = chunk * 8;
        const unsigned sb = smb + (unsigned)stage * (STAGEW * 4);
        cpa16(sb + 0u * (PLANE * 4) + srow4, Aph + ko);
        cpa16(sb + 1u * (PLANE * 4) + srow4, Apl + ko);
        cpa16(sb + 2u * (PLANE * 4) + srow4, Wph + ko);
        cpa16(sb + 3u * (PLANE * 4) + srow4, Wpl + ko);
        cpa_commit();
    };

    issue(0, 0);
    issue(1, 1);

    int cur = 0;
    for (int chunk = 0; chunk < nchunks; ++chunk) {
        if (chunk + 1 < nchunks) cpa_wait<1>(); else cpa_wait<0>();
        __syncthreads();

        const unsigned pb = smb + (unsigned)cur * (STAGEW * 4);

        // B fragments: 2 nt-pairs x (hi, lo)
        unsigned bh[2][4], bl[2][4];
#pragma unroll
        for (int pr = 0; pr < 2; ++pr) {
            const unsigned ba = pb + 2u * (PLANE * 4) + (unsigned)(wn + pr * 16) * PLW * 4 + boff;
            ldsm4(bh[pr][0], bh[pr][1], bh[pr][2], bh[pr][3], ba);
            ldsm4(bl[pr][0], bl[pr][1], bl[pr][2], bl[pr][3], ba + PLANE * 4);
        }

#pragma unroll
        for (int mh = 0; mh < 2; ++mh) {
            unsigned ah[2][4], al[2][4];
#pragma unroll
            for (int m2 = 0; m2 < 2; ++m2) {
                const int rb = wm + (mh * 2 + m2) * 16;
                const unsigned aa = pb + (unsigned)rb * PLW * 4 + aoff;
                ldsm4(ah[m2][0], ah[m2][1], ah[m2][2], ah[m2][3], aa);
                ldsm4(al[m2][0], al[m2][1], al[m2][2], al[m2][3], aa + PLANE * 4);
            }
#pragma unroll
            for (int nt = 0; nt < 4; ++nt) {
                const unsigned b0 = bh[nt >> 1][(nt & 1) * 2];
                const unsigned b1 = bh[nt >> 1][(nt & 1) * 2 + 1];
                const unsigned c0 = bl[nt >> 1][(nt & 1) * 2];
                const unsigned c1 = bl[nt >> 1][(nt & 1) * 2 + 1];
#pragma unroll
                for (int m2 = 0; m2 < 2; ++m2) {
                    float* d = acc[mh * 2 + m2][nt];
                    mma_bf16(d, ah[m2][0], ah[m2][1], ah[m2][2], ah[m2][3], b0, b1); // hh
                    mma_bf16(d, al[m2][0], al[m2][1], al[m2][2], al[m2][3], b0, b1); // lh
                    mma_bf16(d, ah[m2][0], ah[m2][1], ah[m2][2], ah[m2][3], c0, c1); // hl
                }
            }
        }

        if (chunk + 2 < nchunks) {
            // buffer (cur+2)%3 was consumed at chunk-1; all threads passed
            // the sync above after finishing it -> safe to overwrite.
            issue(chunk + 2, (cur + 2 < NSTAGE) ? cur + 2 : cur + 2 - NSTAGE);
        }
        cur = (cur + 1 < NSTAGE) ? cur + 1 : 0;
    }

    if (epi == 3) {
        // k-projection: normalize each row's 32-col head band (warp band = head)
#pragma unroll
        for (int mt = 0; mt < 4; ++mt) {
            float se = 0.f, so = 0.f;
#pragma unroll
            for (int nt = 0; nt < 4; ++nt) {
                se = fmaf(acc[mt][nt][0], acc[mt][nt][0], se);
                se = fmaf(acc[mt][nt][1], acc[mt][nt][1], se);
                so = fmaf(acc[mt][nt][2], acc[mt][nt][2], so);
                so = fmaf(acc[mt][nt][3], acc[mt][nt][3], so);
            }
            se += __shfl_xor_sync(0xffffffffu, se, 1);
            se += __shfl_xor_sync(0xffffffffu, se, 2);
            so += __shfl_xor_sync(0xffffffffu, so, 1);
            so += __shfl_xor_sync(0xffffffffu, so, 2);
            const float ie = __fdividef(1.f, sqrtf(se) + 1e-6f);
            const float io = __fdividef(1.f, sqrtf(so) + 1e-6f);
            const int r0 = row0 + wm + mt * 16 + g;
#pragma unroll
            for (int nt = 0; nt < 4; ++nt) {
                const int cc = col0 + wn + nt * 8 + 2 * c;
                *reinterpret_cast<float2*>(C + (size_t)r0 * Nout + cc) =
                    make_float2(acc[mt][nt][0] * ie, acc[mt][nt][1] * ie);
                *reinterpret_cast<float2*>(C + (size_t)(r0 + 8) * Nout + cc) =
                    make_float2(acc[mt][nt][2] * io, acc[mt][nt][3] * io);
            }
        }
        return;
    }

#pragma unroll
    for (int mt = 0; mt < 4; ++mt) {
        const int r0 = row0 + wm + mt * 16 + g;
#pragma unroll
        for (int nt = 0; nt < 4; ++nt) {
            const int cc = col0 + wn + nt * 8 + 2 * c;
            float d0 = acc[mt][nt][0], d1 = acc[mt][nt][1];
            float d2 = acc[mt][nt][2], d3 = acc[mt][nt][3];
            if (epi == 4) {
                d0 = d0 * __fdividef(1.f, 1.f + __expf(-d0));
                d1 = d1 * __fdividef(1.f, 1.f + __expf(-d1));
                d2 = d2 * __fdividef(1.f, 1.f + __expf(-d2));
                d3 = d3 * __fdividef(1.f, 1.f + __expf(-d3));
                const size_t w0 = ((size_t)r0 * Nout + cc) >> 1;
                const size_t w1 = ((size_t)(r0 + 8) * Nout + cc) >> 1;
                Chi[w0] = pack_hi_pair(d0, d1);
                Clo[w0] = pack_lo_pair(d0 - trunc_hi(d0), d1 - trunc_hi(d1));
                Chi[w1] = pack_hi_pair(d2, d3);
                Clo[w1] = pack_lo_pair(d2 - trunc_hi(d2), d3 - trunc_hi(d3));
                continue;
            }
            if (epi == 2) {
                const float b0 = bias[cc], b1 = bias[cc + 1];
                d0 = __fdividef(1.f, 1.f + __expf(-(d0 + b0)));
                d1 = __fdividef(1.f, 1.f + __expf(-(d1 + b1)));
                d2 = __fdividef(1.f, 1.f + __expf(-(d2 + b0)));
                d3 = __fdividef(1.f, 1.f + __expf(-(d3 + b1)));
            }
            *reinterpret_cast<float2*>(C + (size_t)r0 * Nout + cc)       = make_float2(d0, d1);
            *reinterpret_cast<float2*>(C + (size_t)(r0 + 8) * Nout + cc) = make_float2(d2, d3);
        }
    }
}

template<int EPI>
__global__ void __launch_bounds__(256, 2)
gemm_bf16(const unsigned* __restrict__ Ah, const unsigned* __restrict__ Al,
          const unsigned* __restrict__ Wh, const unsigned* __restrict__ Wl,
          float* __restrict__ C, unsigned* __restrict__ Chi, unsigned* __restrict__ Clo,
          const float* __restrict__ bias, int Nout, int Kw)
{
    mma_gemm_core(Ah, Al, Wh, Wl, C, Chi, Clo, bias, EPI, Nout, Kw,
                  blockIdx.y * 128, blockIdx.x * 128);
}

struct ProjPtrs {
    const unsigned* Wh[4];
    const unsigned* Wl[4];
    float*          C[4];
};

// z: 0 = k (head-band normalize), 1 = v, 2 = q, 3 = beta (sigmoid+bias)
__global__ void __launch_bounds__(256, 2)
gemm_proj4(const unsigned* __restrict__ Ah, const unsigned* __restrict__ Al,
           ProjPtrs p, const float* __restrict__ bias, int Nout, int Kw)
{
    const int z = blockIdx.z;
    const int epi = (z == 0) ? 3 : ((z == 3) ? 2 : 0);
    mma_gemm_core(Ah, Al, p.Wh[z], p.Wl[z], p.C[z], nullptr, nullptr, bias,
                  epi, Nout, Kw, blockIdx.y * 128, blockIdx.x * 128);
}

// ---------------------------------------------------------------------------
// Barrier-free sequential scan (proven round-8/9 tiling: 2 cols/lane,
// 2 rows/warp, 16 warps/chain). Writes cell as split bf16 hi/lo planes.
// ---------------------------------------------------------------------------
#define PF 4

__global__ void __launch_bounds__(128)
scan_kernel(const float* __restrict__ Kn, const float* __restrict__ Vp,
            const float* __restrict__ Qp, const float* __restrict__ Bp,
            unsigned short* __restrict__ cellh, unsigned short* __restrict__ celll,
            float* __restrict__ S_final, int writeS)
{
    const int g     = blockIdx.x * 4 + (threadIdx.x >> 5);
    const int chain = g >> 4;
    const int wc    = g & 15;
    const int l     = threadIdx.x & 31;
    const int i     = wc * 2 + (l >> 4);
    const int j0    = (l & 15) * 2;
    const size_t cb = ((size_t)(chain >> 3) * TT) * HN + (size_t)(chain & 7) * NN;

    float2 pk[PF], pq[PF];
    float  pv[PF], pb[PF];
#pragma unroll
    for (int d = 0; d < PF; ++d) {
        const size_t a = cb + (size_t)d * HN;
        pk[d] = *reinterpret_cast<const float2*>(Kn + a + j0);
        pq[d] = *reinterpret_cast<const float2*>(Qp + a + j0);
        pv[d] = Vp[a + i];
        pb[d] = Bp[a + i];
    }

    float S0 = 0.f, S1 = 0.f, sqp = 0.f;
    size_t base = cb;

    for (int t = 0; t < TT; t += PF) {
#pragma unroll
        for (int u = 0; u < PF; ++u) {
            const int tcur = t + u;
            const int tpre = (tcur + PF < TT) ? (tcur + PF) : (TT - 1);
            const size_t pa = cb + (size_t)tpre * HN;
            const float2 nk = *reinterpret_cast<const float2*>(Kn + pa + j0);
            const float2 nq = *reinterpret_cast<const float2*>(Qp + pa + j0);
            const float  nv = Vp[pa + i];
            const float  nb = Bp[pa + i];

            const float k0 = pk[u].x, k1 = pk[u].y;

            float uu = fmaf(S1, k1, S0 * k0);
            float sv = sqp;
#pragma unroll
            for (int o = 1; o < 16; o <<= 1) {
                uu += __shfl_xor_sync(0xffffffffu, uu, o);
                sv += __shfl_xor_sync(0xffffffffu, sv, o);
            }
            if (tcur > 0 && (l & 15) == 0) {
                const float ov = sv * sv * __fdividef(1.f, 1.f + __expf(-sv));
                cellh[base - HN + i] = (unsigned short)(__float_as_uint(ov) >> 16);
                unsigned short lo16;
                const float res = ov - trunc_hi(ov);
                asm("cvt.rn.bf16.f32 %0, %1;" : "=h"(lo16) : "f"(res));
                celll[base - HN + i] = lo16;
            }

            const float delta = pv[u] - uu;
            const float bi    = pb[u];
            const float z0 = fmaf(bi, S0, delta * k0);
            const float z1 = fmaf(bi, S1, delta * k1);
            const float e0 = __expf(2.f * z0);
            const float e1 = __expf(2.f * z1);
            S0 = 1.f - __fdividef(2.f, e0 + 1.f);
            S1 = 1.f - __fdividef(2.f, e1 + 1.f);

            sqp = fmaf(S1, pq[u].y, S0 * pq[u].x);

            pk[u] = nk; pq[u] = nq; pv[u] = nv; pb[u] = nb;
            base += HN;
        }
    }

    float sv = sqp;
#pragma unroll
    for (int o = 1; o < 16; o <<= 1) sv += __shfl_xor_sync(0xffffffffu, sv, o);
    if ((l & 15) == 0) {
        const float ov = sv * sv * __fdividef(1.f, 1.f + __expf(-sv));
        cellh[base - HN + i] = (unsigned short)(__float_as_uint(ov) >> 16);
        unsigned short lo16;
        const float res = ov - trunc_hi(ov);
        asm("cvt.rn.bf16.f32 %0, %1;" : "=h"(lo16) : "f"(res));
        celll[base - HN + i] = lo16;
    }

    if (writeS) {
        S_final[((size_t)chain * NN + i) * NN + j0]     = S0;
        S_final[((size_t)chain * NN + i) * NN + j0 + 1] = S1;
    }
}

// ---------------------------------------------------------------------------
// Host launcher
// ---------------------------------------------------------------------------
extern "C" void kernel_launch(void* const* d_in, const int* in_sizes, int n_in,
                              void* d_out, int out_size)
{
    const float* x      = (const float*)d_in[0];
    const float* W_in   = (const float*)d_in[1];
    const float* W_k    = (const float*)d_in[2];
    const float* W_v    = (const float*)d_in[3];
    const float* W_q    = (const float*)d_in[4];
    const float* W_beta = (const float*)d_in[5];
    const float* b_beta = (const float*)d_in[6];
    const float* W_out  = (const float*)d_in[7];
    float* y = (float*)d_out;

    unsigned *xh, *xl, *xph, *xpl, *wih, *wil;
    unsigned *wkh, *wkl, *wvh, *wvl, *wqh, *wql, *wbh, *wbl, *woh, *wol;
    float *k, *v, *q, *bt;
    unsigned short *cellh, *celll;
    cudaGetSymbolAddress((void**)&xh,  g_xh);  cudaGetSymbolAddress((void**)&xl,  g_xl);
    cudaGetSymbolAddress((void**)&xph, g_xph); cudaGetSymbolAddress((void**)&xpl, g_xpl);
    cudaGetSymbolAddress((void**)&wih, g_wih); cudaGetSymbolAddress((void**)&wil, g_wil);
    cudaGetSymbolAddress((void**)&wkh, g_wkh); cudaGetSymbolAddress((void**)&wkl, g_wkl);
    cudaGetSymbolAddress((void**)&wvh, g_wvh); cudaGetSymbolAddress((void**)&wvl, g_wvl);
    cudaGetSymbolAddress((void**)&wqh, g_wqh); cudaGetSymbolAddress((void**)&wql, g_wql);
    cudaGetSymbolAddress((void**)&wbh, g_wbh); cudaGetSymbolAddress((void**)&wbl, g_wbl);
    cudaGetSymbolAddress((void**)&woh, g_woh); cudaGetSymbolAddress((void**)&wol, g_wol);
    cudaGetSymbolAddress((void**)&k,  g_k);  cudaGetSymbolAddress((void**)&v,  g_v);
    cudaGetSymbolAddress((void**)&q,  g_q);  cudaGetSymbolAddress((void**)&bt, g_beta);
    cudaGetSymbolAddress((void**)&cellh, g_cellh);
    cudaGetSymbolAddress((void**)&celll, g_celll);

    cudaFuncSetAttribute(gemm_bf16<0>, cudaFuncAttributeMaxDynamicSharedMemorySize, SMEM_GB);
    cudaFuncSetAttribute(gemm_bf16<4>, cudaFuncAttributeMaxDynamicSharedMemorySize, SMEM_GB);
    cudaFuncSetAttribute(gemm_proj4,   cudaFuncAttributeMaxDynamicSharedMemorySize, SMEM_GB);

    const int M = MROWS;

    // 0. split fp32 operands into bf16 hi/lo planes
    split_kernel<<<(M * DD / 2) / 256, 256>>>((const float2*)x, xh, xl, M * DD / 2);
    split_kernel<<<(DD * DD / 2) / 256, 256>>>((const float2*)W_in, wih, wil, DD * DD / 2);
    split_kernel<<<(HN * DD / 2) / 256, 256>>>((const float2*)W_k, wkh, wkl, HN * DD / 2);
    split_kernel<<<(HN * DD / 2) / 256, 256>>>((const float2*)W_v, wvh, wvl, HN * DD / 2);
    split_kernel<<<(HN * DD / 2) / 256, 256>>>((const float2*)W_q, wqh, wql, HN * DD / 2);
    split_kernel<<<(HN * DD / 2) / 256, 256>>>((const float2*)W_beta, wbh, wbl, HN * DD / 2);
    split_kernel<<<(DD * HN / 2) / 256, 256>>>((const float2*)W_out, woh, wol, DD * HN / 2);

    // 1. xp = silu(x @ W_in^T) -> split planes (epi 4)
    gemm_bf16<4><<<dim3(DD / 128, M / 128), 256, SMEM_GB>>>(
        xh, xl, wih, wil, nullptr, xph, xpl, nullptr, DD, DD / 2);

    // 2. fused projections: k (normalized), v, q, beta
    ProjPtrs p;
    p.Wh[0] = wkh; p.Wl[0] = wkl; p.C[0] = k;
    p.Wh[1] = wvh; p.Wl[1] = wvl; p.C[1] = v;
    p.Wh[2] = wqh; p.Wl[2] = wql; p.C[2] = q;
    p.Wh[3] = wbh; p.Wl[3] = wbl; p.C[3] = bt;
    gemm_proj4<<<dim3(HN / 128, M / 128, 4), 256, SMEM_GB>>>(
        xph, xpl, p, b_beta, HN, DD / 2);

    // 3. sequential scan (writes cell as split bf16 planes)
    const size_t y_elems = (size_t)M * DD;
    const int writeS = (out_size >= (int)(y_elems + (size_t)BB * HH * NN * NN)) ? 1 : 0;
    scan_kernel<<<256, 128>>>(k, v, q, bt, cellh, celll, y + y_elems, writeS);

    // 4. y = cell @ W_out^T
    gemm_bf16<0><<<dim3(DD / 128, M / 128), 256, SMEM_GB>>>(
        (const unsigned*)cellh, (const unsigned*)celll, woh, wol,
        y, nullptr, nullptr, nullptr, DD, HN / 2);
}

// round 15
// speedup vs baseline: 1.2148x; 1.0139x over previous
#include <cuda_runtime.h>
#include <cstddef>
#include <cstdint>

// Problem constants
#define BB 8
#define TT 2048
#define DD 1024
#define HH 8
#define NN 32
#define MROWS (BB*TT)          // 16384
#define HN (HH*NN)             // 256

// ---------------------------------------------------------------------------
// Scratch (no cudaMalloc allowed) — __device__ globals.
// Split planes: packed bf16 pairs (one u32 = 2 bf16 along K).
// ---------------------------------------------------------------------------
__device__ unsigned g_xh [(size_t)MROWS * DD / 2];
__device__ unsigned g_xl [(size_t)MROWS * DD / 2];
__device__ unsigned g_xph[(size_t)MROWS * DD / 2];
__device__ unsigned g_xpl[(size_t)MROWS * DD / 2];
__device__ unsigned g_wih[(size_t)DD * DD / 2];
__device__ unsigned g_wil[(size_t)DD * DD / 2];
__device__ unsigned g_wkh[(size_t)HN * DD / 2];
__device__ unsigned g_wkl[(size_t)HN * DD / 2];
__device__ unsigned g_wvh[(size_t)HN * DD / 2];
__device__ unsigned g_wvl[(size_t)HN * DD / 2];
__device__ unsigned g_wqh[(size_t)HN * DD / 2];
__device__ unsigned g_wql[(size_t)HN * DD / 2];
__device__ unsigned g_wbh[(size_t)HN * DD / 2];
__device__ unsigned g_wbl[(size_t)HN * DD / 2];
__device__ unsigned g_woh[(size_t)DD * HN / 2];
__device__ unsigned g_wol[(size_t)DD * HN / 2];
__device__ float    g_k   [(size_t)MROWS * HN];
__device__ float    g_v   [(size_t)MROWS * HN];
__device__ float    g_q   [(size_t)MROWS * HN];
__device__ float    g_beta[(size_t)MROWS * HN];
__device__ unsigned short g_cellh[(size_t)MROWS * HN];
__device__ unsigned short g_celll[(size_t)MROWS * HN];

// ---------------------------------------------------------------------------
// bf16 split helpers
// ---------------------------------------------------------------------------
__device__ __forceinline__ float trunc_hi(float x) {
    return __uint_as_float(__float_as_uint(x) & 0xFFFF0000u);
}
__device__ __forceinline__ unsigned pack_hi_pair(float e0, float e1) {
    return __byte_perm(__float_as_uint(e0), __float_as_uint(e1), 0x7632);
}
__device__ __forceinline__ unsigned pack_lo_pair(float l0, float l1) {
    unsigned d;
    asm("cvt.rn.bf16x2.f32 %0, %1, %2;" : "=r"(d) : "f"(l1), "f"(l0));
    return d;
}

__global__ void __launch_bounds__(256)
split_kernel(const float2* __restrict__ in, unsigned* __restrict__ hi,
             unsigned* __restrict__ lo, int n)
{
    const int i = blockIdx.x * 256 + threadIdx.x;
    if (i < n) {
        const float2 v = in[i];
        hi[i] = pack_hi_pair(v.x, v.y);
        lo[i] = pack_lo_pair(v.x - trunc_hi(v.x), v.y - trunc_hi(v.y));
    }
}

__device__ __forceinline__ void mma_bf16(float d[4],
                                         unsigned a0, unsigned a1,
                                         unsigned a2, unsigned a3,
                                         unsigned b0, unsigned b1) {
    asm("mma.sync.aligned.m16n8k16.row.col.f32.bf16.bf16.f32 "
        "{%0,%1,%2,%3}, {%4,%5,%6,%7}, {%8,%9}, {%0,%1,%2,%3};"
        : "+f"(d[0]), "+f"(d[1]), "+f"(d[2]), "+f"(d[3])
        : "r"(a0), "r"(a1), "r"(a2), "r"(a3), "r"(b0), "r"(b1));
}

__device__ __forceinline__ void ldsm4(unsigned& r0, unsigned& r1,
                                      unsigned& r2, unsigned& r3, unsigned addr) {
    asm volatile("ldmatrix.sync.aligned.m8n8.x4.shared.b16 {%0,%1,%2,%3}, [%4];"
                 : "=r"(r0), "=r"(r1), "=r"(r2), "=r"(r3) : "r"(addr));
}

// cp.async helpers (L2 -> smem, bypassing L1/register round trip)
__device__ __forceinline__ void cpa16(unsigned dst, const void* src) {
    asm volatile("cp.async.cg.shared.global [%0], [%1], 16;" :: "r"(dst), "l"(src));
}
__device__ __forceinline__ void cpa_commit() {
    asm volatile("cp.async.commit_group;" ::: "memory");
}
template<int N>
__device__ __forceinline__ void cpa_wait() {
    asm volatile("cp.async.wait_group %0;" :: "n"(N) : "memory");
}

// ---------------------------------------------------------------------------
// bf16x2-compensated tensor GEMM (proven 64x32 warp tile) with 4-stage
// cp.async pipeline (wait_group 2 -> two chunks of copy slack).
// C = epi( A @ W^T ). Block 128x128, chunk k16 (8 u32 words), 8 warps 2Mx4N,
// 256 threads, 2 CTAs/SM. Per chunk per warp: 12 ldmatrix.x4 + 48 HMMA.
// epi: 0 identity(f32), 2 sigmoid(acc+bias), 3 head-band row-norm,
//      4 silu + split-write
// ---------------------------------------------------------------------------
#define PLW 12
#define PLANE (128 * PLW)           // u32 per plane (1536)
#define STAGEW (4 * PLANE)          // u32 per stage (6144)
#define NSTAGE 4
#define SMEM_GB (NSTAGE * STAGEW * 4)   // 98304 bytes

__device__ __forceinline__ void mma_gemm_core(
    const unsigned* __restrict__ Ah, const unsigned* __restrict__ Al,
    const unsigned* __restrict__ Wh, const unsigned* __restrict__ Wl,
    float* __restrict__ C, unsigned* __restrict__ Chi, unsigned* __restrict__ Clo,
    const float* __restrict__ bias,
    int epi, int Nout, int Kw, int row0, int col0)
{
    extern __shared__ unsigned sm[];   // [NSTAGE][STAGEW]

    const int tid  = threadIdx.x;
    const int wid  = tid >> 5;
    const int lane = tid & 31;
    const int g    = lane >> 2;
    const int c    = lane & 3;
    const int wm   = (wid & 1) * 64;
    const int wn   = (wid >> 1) * 32;

    // staging: thread covers row lr, word-half wsel (16B per plane per chunk)
    const int lr   = tid >> 1;
    const int wsel = tid & 1;
    const unsigned* Aph = Ah + (size_t)(row0 + lr) * Kw + wsel * 4;
    const unsigned* Apl = Al + (size_t)(row0 + lr) * Kw + wsel * 4;
    const unsigned* Wph = Wh + (size_t)(col0 + lr) * Kw + wsel * 4;
    const unsigned* Wpl = Wl + (size_t)(col0 + lr) * Kw + wsel * 4;
    const unsigned srow4 = (unsigned)(lr * PLW + wsel * 4) * 4;  // byte offset in plane

    const unsigned smb = (unsigned)__cvta_generic_to_shared(&sm[0]);
    const unsigned aoff = (((lane & 15) * PLW) + ((lane >> 4) << 2)) * 4;
    const unsigned boff = ((((lane >> 4) * 8 + (lane & 7)) * PLW) + ((lane & 8) ? 4 : 0)) * 4;

    float acc[4][4][4];
#pragma unroll
    for (int mt = 0; mt < 4; ++mt)
#pragma unroll
        for (int nt = 0; nt < 4; ++nt)
#pragma unroll
            for (int e = 0; e < 4; ++e) acc[mt][nt][e] = 0.f;

    const int nchunks = Kw / 8;    // >= 16 for all our shapes

    // issue one chunk's copies into a stage (4 x 16B per thread) + commit
    auto issue = [&](int chunk, int stage) {
        const int ko = chunk * 8;
        const unsigned sb = smb + (unsigned)stage * (STAGEW * 4);
        cpa16(sb + 0u * (PLANE * 4) + srow4, Aph + ko);
        cpa16(sb + 1u * (PLANE * 4) + srow4, Apl + ko);
        cpa16(sb + 2u * (PLANE * 4) + srow4, Wph + ko);
        cpa16(sb + 3u * (PLANE * 4) + srow4, Wpl + ko);
        cpa_commit();
    };

    issue(0, 0);
    issue(1, 1);
    issue(2, 2);

    int cur = 0;
    for (int chunk = 0; chunk < nchunks; ++chunk) {
        // guarantee group `chunk` completed (pending <= issued - chunk - 1)
        if (chunk + 3 <= nchunks)      cpa_wait<2>();
        else if (chunk + 2 == nchunks) cpa_wait<1>();
        else                           cpa_wait<0>();
        __syncthreads();

        const unsigned pb = smb + (unsigned)cur * (STAGEW * 4);

        // B fragments: 2 nt-pairs x (hi, lo)
        unsigned bh[2][4], bl[2][4];
#pragma unroll
        for (int pr = 0; pr < 2; ++pr) {
            const unsigned ba = pb + 2u * (PLANE * 4) + (unsigned)(wn + pr * 16) * PLW * 4 + boff;
            ldsm4(bh[pr][0], bh[pr][1], bh[pr][2], bh[pr][3], ba);
            ldsm4(bl[pr][0], bl[pr][1], bl[pr][2], bl[pr][3], ba + PLANE * 4);
        }

#pragma unroll
        for (int mh = 0; mh < 2; ++mh) {
            unsigned ah[2][4], al[2][4];
#pragma unroll
            for (int m2 = 0; m2 < 2; ++m2) {
                const int rb = wm + (mh * 2 + m2) * 16;
                const unsigned aa = pb + (unsigned)rb * PLW * 4 + aoff;
                ldsm4(ah[m2][0], ah[m2][1], ah[m2][2], ah[m2][3], aa);
                ldsm4(al[m2][0], al[m2][1], al[m2][2], al[m2][3], aa + PLANE * 4);
            }
#pragma unroll
            for (int nt = 0; nt < 4; ++nt) {
                const unsigned b0 = bh[nt >> 1][(nt & 1) * 2];
                const unsigned b1 = bh[nt >> 1][(nt & 1) * 2 + 1];
                const unsigned c0 = bl[nt >> 1][(nt & 1) * 2];
                const unsigned c1 = bl[nt >> 1][(nt & 1) * 2 + 1];
#pragma unroll
                for (int m2 = 0; m2 < 2; ++m2) {
                    float* d = acc[mh * 2 + m2][nt];
                    mma_bf16(d, ah[m2][0], ah[m2][1], ah[m2][2], ah[m2][3], b0, b1); // hh
                    mma_bf16(d, al[m2][0], al[m2][1], al[m2][2], al[m2][3], b0, b1); // lh
                    mma_bf16(d, ah[m2][0], ah[m2][1], ah[m2][2], ah[m2][3], c0, c1); // hl
                }
            }
        }

        if (chunk + 3 < nchunks) {
            // stage (cur+3)&3 held chunk-1's data; every warp past sync(chunk)
            // has finished computing chunk-1 -> safe to overwrite.
            issue(chunk + 3, (cur + 3) & 3);
        }
        cur = (cur + 1) & 3;
    }

    if (epi == 3) {
        // k-projection: normalize each row's 32-col head band (warp band = head)
#pragma unroll
        for (int mt = 0; mt < 4; ++mt) {
            float se = 0.f, so = 0.f;
#pragma unroll
            for (int nt = 0; nt < 4; ++nt) {
                se = fmaf(acc[mt][nt][0], acc[mt][nt][0], se);
                se = fmaf(acc[mt][nt][1], acc[mt][nt][1], se);
                so = fmaf(acc[mt][nt][2], acc[mt][nt][2], so);
                so = fmaf(acc[mt][nt][3], acc[mt][nt][3], so);
            }
            se += __shfl_xor_sync(0xffffffffu, se, 1);
            se += __shfl_xor_sync(0xffffffffu, se, 2);
            so += __shfl_xor_sync(0xffffffffu, so, 1);
            so += __shfl_xor_sync(0xffffffffu, so, 2);
            const float ie = __fdividef(1.f, sqrtf(se) + 1e-6f);
            const float io = __fdividef(1.f, sqrtf(so) + 1e-6f);
            const int r0 = row0 + wm + mt * 16 + g;
#pragma unroll
            for (int nt = 0; nt < 4; ++nt) {
                const int cc = col0 + wn + nt * 8 + 2 * c;
                *reinterpret_cast<float2*>(C + (size_t)r0 * Nout + cc) =
                    make_float2(acc[mt][nt][0] * ie, acc[mt][nt][1] * ie);
                *reinterpret_cast<float2*>(C + (size_t)(r0 + 8) * Nout + cc) =
                    make_float2(acc[mt][nt][2] * io, acc[mt][nt][3] * io);
            }
        }
        return;
    }

#pragma unroll
    for (int mt = 0; mt < 4; ++mt) {
        const int r0 = row0 + wm + mt * 16 + g;
#pragma unroll
        for (int nt = 0; nt < 4; ++nt) {
            const int cc = col0 + wn + nt * 8 + 2 * c;
            float d0 = acc[mt][nt][0], d1 = acc[mt][nt][1];
            float d2 = acc[mt][nt][2], d3 = acc[mt][nt][3];
            if (epi == 4) {
                d0 = d0 * __fdividef(1.f, 1.f + __expf(-d0));
                d1 = d1 * __fdividef(1.f, 1.f + __expf(-d1));
                d2 = d2 * __fdividef(1.f, 1.f + __expf(-d2));
                d3 = d3 * __fdividef(1.f, 1.f + __expf(-d3));
                const size_t w0 = ((size_t)r0 * Nout + cc) >> 1;
                const size_t w1 = ((size_t)(r0 + 8) * Nout + cc) >> 1;
                Chi[w0] = pack_hi_pair(d0, d1);
                Clo[w0] = pack_lo_pair(d0 - trunc_hi(d0), d1 - trunc_hi(d1));
                Chi[w1] = pack_hi_pair(d2, d3);
                Clo[w1] = pack_lo_pair(d2 - trunc_hi(d2), d3 - trunc_hi(d3));
                continue;
            }
            if (epi == 2) {
                const float b0 = bias[cc], b1 = bias[cc + 1];
                d0 = __fdividef(1.f, 1.f + __expf(-(d0 + b0)));
                d1 = __fdividef(1.f, 1.f + __expf(-(d1 + b1)));
                d2 = __fdividef(1.f, 1.f + __expf(-(d2 + b0)));
                d3 = __fdividef(1.f, 1.f + __expf(-(d3 + b1)));
            }
            *reinterpret_cast<float2*>(C + (size_t)r0 * Nout + cc)       = make_float2(d0, d1);
            *reinterpret_cast<float2*>(C + (size_t)(r0 + 8) * Nout + cc) = make_float2(d2, d3);
        }
    }
}

template<int EPI>
__global__ void __launch_bounds__(256, 2)
gemm_bf16(const unsigned* __restrict__ Ah, const unsigned* __restrict__ Al,
          const unsigned* __restrict__ Wh, const unsigned* __restrict__ Wl,
          float* __restrict__ C, unsigned* __restrict__ Chi, unsigned* __restrict__ Clo,
          const float* __restrict__ bias, int Nout, int Kw)
{
    mma_gemm_core(Ah, Al, Wh, Wl, C, Chi, Clo, bias, EPI, Nout, Kw,
                  blockIdx.y * 128, blockIdx.x * 128);
}

struct ProjPtrs {
    const unsigned* Wh[4];
    const unsigned* Wl[4];
    float*          C[4];
};

// z: 0 = k (head-band normalize), 1 = v, 2 = q, 3 = beta (sigmoid+bias)
__global__ void __launch_bounds__(256, 2)
gemm_proj4(const unsigned* __restrict__ Ah, const unsigned* __restrict__ Al,
           ProjPtrs p, const float* __restrict__ bias, int Nout, int Kw)
{
    const int z = blockIdx.z;
    const int epi = (z == 0) ? 3 : ((z == 3) ? 2 : 0);
    mma_gemm_core(Ah, Al, p.Wh[z], p.Wl[z], p.C[z], nullptr, nullptr, bias,
                  epi, Nout, Kw, blockIdx.y * 128, blockIdx.x * 128);
}

// ---------------------------------------------------------------------------
// Barrier-free sequential scan (proven round-8/9 tiling: 2 cols/lane,
// 2 rows/warp, 16 warps/chain). On-chain S·kn butterfly issued first,
// off-chain S·q butterfly after. Writes cell as split bf16 hi/lo planes.
// ---------------------------------------------------------------------------
#define PF 4

__global__ void __launch_bounds__(128)
scan_kernel(const float* __restrict__ Kn, const float* __restrict__ Vp,
            const float* __restrict__ Qp, const float* __restrict__ Bp,
            unsigned short* __restrict__ cellh, unsigned short* __restrict__ celll,
            float* __restrict__ S_final, int writeS)
{
    const int g     = blockIdx.x * 4 + (threadIdx.x >> 5);
    const int chain = g >> 4;
    const int wc    = g & 15;
    const int l     = threadIdx.x & 31;
    const int i     = wc * 2 + (l >> 4);
    const int j0    = (l & 15) * 2;
    const size_t cb = ((size_t)(chain >> 3) * TT) * HN + (size_t)(chain & 7) * NN;

    float2 pk[PF], pq[PF];
    float  pv[PF], pb[PF];
#pragma unroll
    for (int d = 0; d < PF; ++d) {
        const size_t a = cb + (size_t)d * HN;
        pk[d] = *reinterpret_cast<const float2*>(Kn + a + j0);
        pq[d] = *reinterpret_cast<const float2*>(Qp + a + j0);
        pv[d] = Vp[a + i];
        pb[d] = Bp[a + i];
    }

    float S0 = 0.f, S1 = 0.f, sqp = 0.f;
    size_t base = cb;

    for (int t = 0; t < TT; t += PF) {
#pragma unroll
        for (int u = 0; u < PF; ++u) {
            const int tcur = t + u;
            const int tpre = (tcur + PF < TT) ? (tcur + PF) : (TT - 1);
            const size_t pa = cb + (size_t)tpre * HN;
            const float2 nk = *reinterpret_cast<const float2*>(Kn + pa + j0);
            const float2 nq = *reinterpret_cast<const float2*>(Qp + pa + j0);
            const float  nv = Vp[pa + i];
            const float  nb = Bp[pa + i];

            const float k0 = pk[u].x, k1 = pk[u].y;

            // on-chain reduction first (S·kn), then off-chain (prev S·q)
            float uu = fmaf(S1, k1, S0 * k0);
#pragma unroll
            for (int o = 1; o < 16; o <<= 1)
                uu += __shfl_xor_sync(0xffffffffu, uu, o);
            float sv = sqp;
#pragma unroll
            for (int o = 1; o < 16; o <<= 1)
                sv += __shfl_xor_sync(0xffffffffu, sv, o);

            if (tcur > 0 && (l & 15) == 0) {
                const float ov = sv * sv * __fdividef(1.f, 1.f + __expf(-sv));
                cellh[base - HN + i] = (unsigned short)(__float_as_uint(ov) >> 16);
                unsigned short lo16;
                const float res = ov - trunc_hi(ov);
                asm("cvt.rn.bf16.f32 %0, %1;" : "=h"(lo16) : "f"(res));
                celll[base - HN + i] = lo16;
            }

            const float delta = pv[u] - uu;
            const float bi    = pb[u];
            const float z0 = fmaf(bi, S0, delta * k0);
            const float z1 = fmaf(bi, S1, delta * k1);
            const float e0 = __expf(2.f * z0);
            const float e1 = __expf(2.f * z1);
            S0 = 1.f - __fdividef(2.f, e0 + 1.f);
            S1 = 1.f - __fdividef(2.f, e1 + 1.f);

            sqp = fmaf(S1, pq[u].y, S0 * pq[u].x);

            pk[u] = nk; pq[u] = nq; pv[u] = nv; pb[u] = nb;
            base += HN;
        }
    }

    float sv = sqp;
#pragma unroll
    for (int o = 1; o < 16; o <<= 1) sv += __shfl_xor_sync(0xffffffffu, sv, o);
    if ((l & 15) == 0) {
        const float ov = sv * sv * __fdividef(1.f, 1.f + __expf(-sv));
        cellh[base - HN + i] = (unsigned short)(__float_as_uint(ov) >> 16);
        unsigned short lo16;
        const float res = ov - trunc_hi(ov);
        asm("cvt.rn.bf16.f32 %0, %1;" : "=h"(lo16) : "f"(res));
        celll[base - HN + i] = lo16;
    }

    if (writeS) {
        S_final[((size_t)chain * NN + i) * NN + j0]     = S0;
        S_final[((size_t)chain * NN + i) * NN + j0 + 1] = S1;
    }
}

// ---------------------------------------------------------------------------
// Host launcher
// ---------------------------------------------------------------------------
extern "C" void kernel_launch(void* const* d_in, const int* in_sizes, int n_in,
                              void* d_out, int out_size)
{
    const float* x      = (const float*)d_in[0];
    const float* W_in   = (const float*)d_in[1];
    const float* W_k    = (const float*)d_in[2];
    const float* W_v    = (const float*)d_in[3];
    const float* W_q    = (const float*)d_in[4];
    const float* W_beta = (const float*)d_in[5];
    const float* b_beta = (const float*)d_in[6];
    const float* W_out  = (const float*)d_in[7];
    float* y = (float*)d_out;

    unsigned *xh, *xl, *xph, *xpl, *wih, *wil;
    unsigned *wkh, *wkl, *wvh, *wvl, *wqh, *wql, *wbh, *wbl, *woh, *wol;
    float *k, *v, *q, *bt;
    unsigned short *cellh, *celll;
    cudaGetSymbolAddress((void**)&xh,  g_xh);  cudaGetSymbolAddress((void**)&xl,  g_xl);
    cudaGetSymbolAddress((void**)&xph, g_xph); cudaGetSymbolAddress((void**)&xpl, g_xpl);
    cudaGetSymbolAddress((void**)&wih, g_wih); cudaGetSymbolAddress((void**)&wil, g_wil);
    cudaGetSymbolAddress((void**)&wkh, g_wkh); cudaGetSymbolAddress((void**)&wkl, g_wkl);
    cudaGetSymbolAddress((void**)&wvh, g_wvh); cudaGetSymbolAddress((void**)&wvl, g_wvl);
    cudaGetSymbolAddress((void**)&wqh, g_wqh); cudaGetSymbolAddress((void**)&wql, g_wql);
    cudaGetSymbolAddress((void**)&wbh, g_wbh); cudaGetSymbolAddress((void**)&wbl, g_wbl);
    cudaGetSymbolAddress((void**)&woh, g_woh); cudaGetSymbolAddress((void**)&wol, g_wol);
    cudaGetSymbolAddress((void**)&k,  g_k);  cudaGetSymbolAddress((void**)&v,  g_v);
    cudaGetSymbolAddress((void**)&q,  g_q);  cudaGetSymbolAddress((void**)&bt, g_beta);
    cudaGetSymbolAddress((void**)&cellh, g_cellh);
    cudaGetSymbolAddress((void**)&celll, g_celll);

    cudaFuncSetAttribute(gemm_bf16<0>, cudaFuncAttributeMaxDynamicSharedMemorySize, SMEM_GB);
    cudaFuncSetAttribute(gemm_bf16<4>, cudaFuncAttributeMaxDynamicSharedMemorySize, SMEM_GB);
    cudaFuncSetAttribute(gemm_proj4,   cudaFuncAttributeMaxDynamicSharedMemorySize, SMEM_GB);

    const int M = MROWS;

    // 0. split fp32 operands into bf16 hi/lo planes
    split_kernel<<<(M * DD / 2) / 256, 256>>>((const float2*)x, xh, xl, M * DD / 2);
    split_kernel<<<(DD * DD / 2) / 256, 256>>>((const float2*)W_in, wih, wil, DD * DD / 2);
    split_kernel<<<(HN * DD / 2) / 256, 256>>>((const float2*)W_k, wkh, wkl, HN * DD / 2);
    split_kernel<<<(HN * DD / 2) / 256, 256>>>((const float2*)W_v, wvh, wvl, HN * DD / 2);
    split_kernel<<<(HN * DD / 2) / 256, 256>>>((const float2*)W_q, wqh, wql, HN * DD / 2);
    split_kernel<<<(HN * DD / 2) / 256, 256>>>((const float2*)W_beta, wbh, wbl, HN * DD / 2);
    split_kernel<<<(DD * HN / 2) / 256, 256>>>((const float2*)W_out, woh, wol, DD * HN / 2);

    // 1. xp = silu(x @ W_in^T) -> split planes (epi 4)
    gemm_bf16<4><<<dim3(DD / 128, M / 128), 256, SMEM_GB>>>(
        xh, xl, wih, wil, nullptr, xph, xpl, nullptr, DD, DD / 2);

    // 2. fused projections: k (normalized), v, q, beta
    ProjPtrs p;
    p.Wh[0] = wkh; p.Wl[0] = wkl; p.C[0] = k;
    p.Wh[1] = wvh; p.Wl[1] = wvl; p.C[1] = v;
    p.Wh[2] = wqh; p.Wl[2] = wql; p.C[2] = q;
    p.Wh[3] = wbh; p.Wl[3] = wbl; p.C[3] = bt;
    gemm_proj4<<<dim3(HN / 128, M / 128, 4), 256, SMEM_GB>>>(
        xph, xpl, p, b_beta, HN, DD / 2);

    // 3. sequential scan (writes cell as split bf16 planes)
    const size_t y_elems = (size_t)M * DD;
    const int writeS = (out_size >= (int)(y_elems + (size_t)BB * HH * NN * NN)) ? 1 : 0;
    scan_kernel<<<256, 128>>>(k, v, q, bt, cellh, celll, y + y_elems, writeS);

    // 4. y = cell @ W_out^T
    gemm_bf16<0><<<dim3(DD / 128, M / 128), 256, SMEM_GB>>>(
        (const unsigned*)cellh, (const unsigned*)celll, woh, wol,
        y, nullptr, nullptr, nullptr, DD, HN / 2);
}

// round 16
// speedup vs baseline: 1.3696x; 1.1274x over previous
#include <cuda_runtime.h>
#include <cstddef>
#include <cstdint>

// Problem constants
#define BB 8
#define TT 2048
#define DD 1024
#define HH 8
#define NN 32
#define MROWS (BB*TT)          // 16384
#define HN (HH*NN)             // 256

// ---------------------------------------------------------------------------
// Scratch (no cudaMalloc allowed) — __device__ globals.
// fp16 planes: packed f16 pairs (one u32 = 2 fp16 along K).
// A-side (x, xp, cell): hi + lo planes (22-bit combined mantissa).
// W-side: single rounded fp16 plane (residual dropped, ~2^-12 relative).
// ---------------------------------------------------------------------------
__device__ unsigned g_xh [(size_t)MROWS * DD / 2];
__device__ unsigned g_xl [(size_t)MROWS * DD / 2];
__device__ unsigned g_xph[(size_t)MROWS * DD / 2];
__device__ unsigned g_xpl[(size_t)MROWS * DD / 2];
__device__ unsigned g_wih[(size_t)DD * DD / 2];
__device__ unsigned g_wkh[(size_t)HN * DD / 2];
__device__ unsigned g_wvh[(size_t)HN * DD / 2];
__device__ unsigned g_wqh[(size_t)HN * DD / 2];
__device__ unsigned g_wbh[(size_t)HN * DD / 2];
__device__ unsigned g_woh[(size_t)DD * HN / 2];
__device__ float    g_k   [(size_t)MROWS * HN];
__device__ float    g_v   [(size_t)MROWS * HN];
__device__ float    g_q   [(size_t)MROWS * HN];
__device__ float    g_beta[(size_t)MROWS * HN];
__device__ unsigned short g_cellh[(size_t)MROWS * HN];
__device__ unsigned short g_celll[(size_t)MROWS * HN];

// ---------------------------------------------------------------------------
// fp16 split helpers
// ---------------------------------------------------------------------------
__device__ __forceinline__ unsigned short f2h(float x) {
    unsigned short h;
    asm("cvt.rn.f16.f32 %0, %1;" : "=h"(h) : "f"(x));
    return h;
}
__device__ __forceinline__ float h2f(unsigned short h) {
    float r;
    asm("cvt.f32.f16 %0, %1;" : "=f"(r) : "h"(h));
    return r;
}
// fp16 value of x, returned as fp32 (for exact residual computation)
__device__ __forceinline__ float hi_f16(float x) { return h2f(f2h(x)); }
// pack fp16(e0), fp16(e1) into one .b32: lo half = e0
__device__ __forceinline__ unsigned pack_f16_pair(float e0, float e1) {
    unsigned d;
    asm("cvt.rn.f16x2.f32 %0, %1, %2;" : "=r"(d) : "f"(e1), "f"(e0));
    return d;
}

// x -> hi/lo planes (A-side)
__global__ void __launch_bounds__(256)
split_kernel(const float2* __restrict__ in, unsigned* __restrict__ hi,
             unsigned* __restrict__ lo, int n)
{
    const int i = blockIdx.x * 256 + threadIdx.x;
    if (i < n) {
        const float2 v = in[i];
        hi[i] = pack_f16_pair(v.x, v.y);
        lo[i] = pack_f16_pair(v.x - hi_f16(v.x), v.y - hi_f16(v.y));
    }
}

// W -> single rounded fp16 plane
__global__ void __launch_bounds__(256)
cvt_kernel(const float2* __restrict__ in, unsigned* __restrict__ hi, int n)
{
    const int i = blockIdx.x * 256 + threadIdx.x;
    if (i < n) {
        const float2 v = in[i];
        hi[i] = pack_f16_pair(v.x, v.y);
    }
}

__device__ __forceinline__ void mma_f16(float d[4],
                                        unsigned a0, unsigned a1,
                                        unsigned a2, unsigned a3,
                                        unsigned b0, unsigned b1) {
    asm("mma.sync.aligned.m16n8k16.row.col.f32.f16.f16.f32 "
        "{%0,%1,%2,%3}, {%4,%5,%6,%7}, {%8,%9}, {%0,%1,%2,%3};"
        : "+f"(d[0]), "+f"(d[1]), "+f"(d[2]), "+f"(d[3])
        : "r"(a0), "r"(a1), "r"(a2), "r"(a3), "r"(b0), "r"(b1));
}

__device__ __forceinline__ void ldsm4(unsigned& r0, unsigned& r1,
                                      unsigned& r2, unsigned& r3, unsigned addr) {
    asm volatile("ldmatrix.sync.aligned.m8n8.x4.shared.b16 {%0,%1,%2,%3}, [%4];"
                 : "=r"(r0), "=r"(r1), "=r"(r2), "=r"(r3) : "r"(addr));
}

// cp.async helpers (L2 -> smem)
__device__ __forceinline__ void cpa16(unsigned dst, const void* src) {
    asm volatile("cp.async.cg.shared.global [%0], [%1], 16;" :: "r"(dst), "l"(src));
}
__device__ __forceinline__ void cpa_commit() {
    asm volatile("cp.async.commit_group;" ::: "memory");
}
template<int N>
__device__ __forceinline__ void cpa_wait() {
    asm volatile("cp.async.wait_group %0;" :: "n"(N) : "memory");
}

// ---------------------------------------------------------------------------
// fp16 2-term compensated tensor GEMM: C = epi( (A_hi + A_lo) @ W^T ).
// Block 128x128, chunk k16 (8 u32 words), 8 warps 2Mx4N (64x32 warp tile),
// 256 threads, 2 CTAs/SM, 4-stage cp.async ring (wait_group 2).
// 3 smem planes per stage (A_hi, A_lo, W). Per chunk per warp:
// 10 ldmatrix.x4 + 32 HMMA.
// epi: 0 identity(f32), 2 sigmoid(acc+bias), 3 head-band row-norm,
//      4 silu + fp16-split-write
// ---------------------------------------------------------------------------
#define PLW 12
#define PLANE (128 * PLW)           // u32 per plane (1536)
#define STAGEW (3 * PLANE)          // u32 per stage (4608)
#define NSTAGE 4
#define SMEM_GB (NSTAGE * STAGEW * 4)   // 73728 bytes

__device__ __forceinline__ void mma_gemm_core(
    const unsigned* __restrict__ Ah, const unsigned* __restrict__ Al,
    const unsigned* __restrict__ Wh,
    float* __restrict__ C, unsigned* __restrict__ Chi, unsigned* __restrict__ Clo,
    const float* __restrict__ bias,
    int epi, int Nout, int Kw, int row0, int col0)
{
    extern __shared__ unsigned sm[];   // [NSTAGE][STAGEW]

    const int tid  = threadIdx.x;
    const int wid  = tid >> 5;
    const int lane = tid & 31;
    const int g    = lane >> 2;
    const int c    = lane & 3;
    const int wm   = (wid & 1) * 64;
    const int wn   = (wid >> 1) * 32;

    // staging: thread covers row lr, word-half wsel (16B per plane per chunk)
    const int lr   = tid >> 1;
    const int wsel = tid & 1;
    const unsigned* Aph = Ah + (size_t)(row0 + lr) * Kw + wsel * 4;
    const unsigned* Apl = Al + (size_t)(row0 + lr) * Kw + wsel * 4;
    const unsigned* Wph = Wh + (size_t)(col0 + lr) * Kw + wsel * 4;
    const unsigned srow4 = (unsigned)(lr * PLW + wsel * 4) * 4;  // byte offset in plane

    const unsigned smb = (unsigned)__cvta_generic_to_shared(&sm[0]);
    const unsigned aoff = (((lane & 15) * PLW) + ((lane >> 4) << 2)) * 4;
    const unsigned boff = ((((lane >> 4) * 8 + (lane & 7)) * PLW) + ((lane & 8) ? 4 : 0)) * 4;

    float acc[4][4][4];
#pragma unroll
    for (int mt = 0; mt < 4; ++mt)
#pragma unroll
        for (int nt = 0; nt < 4; ++nt)
#pragma unroll
            for (int e = 0; e < 4; ++e) acc[mt][nt][e] = 0.f;

    const int nchunks = Kw / 8;    // >= 16 for all our shapes

    // issue one chunk's copies into a stage (3 x 16B per thread) + commit
    auto issue = [&](int chunk, int stage) {
        const int ko = chunk * 8;
        const unsigned sb = smb + (unsigned)stage * (STAGEW * 4);
        cpa16(sb + 0u * (PLANE * 4) + srow4, Aph + ko);
        cpa16(sb + 1u * (PLANE * 4) + srow4, Apl + ko);
        cpa16(sb + 2u * (PLANE * 4) + srow4, Wph + ko);
        cpa_commit();
    };

    issue(0, 0);
    issue(1, 1);
    issue(2, 2);

    int cur = 0;
    for (int chunk = 0; chunk < nchunks; ++chunk) {
        if (chunk + 3 <= nchunks)      cpa_wait<2>();
        else if (chunk + 2 == nchunks) cpa_wait<1>();
        else                           cpa_wait<0>();
        __syncthreads();

        const unsigned pb = smb + (unsigned)cur * (STAGEW * 4);

        // B (W) fragments: 2 nt-pairs
        unsigned bh[2][4];
#pragma unroll
        for (int pr = 0; pr < 2; ++pr) {
            const unsigned ba = pb + 2u * (PLANE * 4) + (unsigned)(wn + pr * 16) * PLW * 4 + boff;
            ldsm4(bh[pr][0], bh[pr][1], bh[pr][2], bh[pr][3], ba);
        }

#pragma unroll
        for (int mh = 0; mh < 2; ++mh) {
            unsigned ah[2][4], al[2][4];
#pragma unroll
            for (int m2 = 0; m2 < 2; ++m2) {
                const int rb = wm + (mh * 2 + m2) * 16;
                const unsigned aa = pb + (unsigned)rb * PLW * 4 + aoff;
                ldsm4(ah[m2][0], ah[m2][1], ah[m2][2], ah[m2][3], aa);
                ldsm4(al[m2][0], al[m2][1], al[m2][2], al[m2][3], aa + PLANE * 4);
            }
#pragma unroll
            for (int nt = 0; nt < 4; ++nt) {
                const unsigned b0 = bh[nt >> 1][(nt & 1) * 2];
                const unsigned b1 = bh[nt >> 1][(nt & 1) * 2 + 1];
#pragma unroll
                for (int m2 = 0; m2 < 2; ++m2) {
                    float* d = acc[mh * 2 + m2][nt];
                    mma_f16(d, ah[m2][0], ah[m2][1], ah[m2][2], ah[m2][3], b0, b1); // hi term
                    mma_f16(d, al[m2][0], al[m2][1], al[m2][2], al[m2][3], b0, b1); // lo term
                }
            }
        }

        if (chunk + 3 < nchunks) {
            issue(chunk + 3, (cur + 3) & 3);
        }
        cur = (cur + 1) & 3;
    }

    if (epi == 3) {
        // k-projection: normalize each row's 32-col head band (warp band = head)
#pragma unroll
        for (int mt = 0; mt < 4; ++mt) {
            float se = 0.f, so = 0.f;
#pragma unroll
            for (int nt = 0; nt < 4; ++nt) {
                se = fmaf(acc[mt][nt][0], acc[mt][nt][0], se);
                se = fmaf(acc[mt][nt][1], acc[mt][nt][1], se);
                so = fmaf(acc[mt][nt][2], acc[mt][nt][2], so);
                so = fmaf(acc[mt][nt][3], acc[mt][nt][3], so);
            }
            se += __shfl_xor_sync(0xffffffffu, se, 1);
            se += __shfl_xor_sync(0xffffffffu, se, 2);
            so += __shfl_xor_sync(0xffffffffu, so, 1);
            so += __shfl_xor_sync(0xffffffffu, so, 2);
            const float ie = __fdividef(1.f, sqrtf(se) + 1e-6f);
            const float io = __fdividef(1.f, sqrtf(so) + 1e-6f);
            const int r0 = row0 + wm + mt * 16 + g;
#pragma unroll
            for (int nt = 0; nt < 4; ++nt) {
                const int cc = col0 + wn + nt * 8 + 2 * c;
                *reinterpret_cast<float2*>(C + (size_t)r0 * Nout + cc) =
                    make_float2(acc[mt][nt][0] * ie, acc[mt][nt][1] * ie);
                *reinterpret_cast<float2*>(C + (size_t)(r0 + 8) * Nout + cc) =
                    make_float2(acc[mt][nt][2] * io, acc[mt][nt][3] * io);
            }
        }
        return;
    }

#pragma unroll
    for (int mt = 0; mt < 4; ++mt) {
        const int r0 = row0 + wm + mt * 16 + g;
#pragma unroll
        for (int nt = 0; nt < 4; ++nt) {
            const int cc = col0 + wn + nt * 8 + 2 * c;
            float d0 = acc[mt][nt][0], d1 = acc[mt][nt][1];
            float d2 = acc[mt][nt][2], d3 = acc[mt][nt][3];
            if (epi == 4) {
                d0 = d0 * __fdividef(1.f, 1.f + __expf(-d0));
                d1 = d1 * __fdividef(1.f, 1.f + __expf(-d1));
                d2 = d2 * __fdividef(1.f, 1.f + __expf(-d2));
                d3 = d3 * __fdividef(1.f, 1.f + __expf(-d3));
                const size_t w0 = ((size_t)r0 * Nout + cc) >> 1;
                const size_t w1 = ((size_t)(r0 + 8) * Nout + cc) >> 1;
                Chi[w0] = pack_f16_pair(d0, d1);
                Clo[w0] = pack_f16_pair(d0 - hi_f16(d0), d1 - hi_f16(d1));
                Chi[w1] = pack_f16_pair(d2, d3);
                Clo[w1] = pack_f16_pair(d2 - hi_f16(d2), d3 - hi_f16(d3));
                continue;
            }
            if (epi == 2) {
                const float b0 = bias[cc], b1 = bias[cc + 1];
                d0 = __fdividef(1.f, 1.f + __expf(-(d0 + b0)));
                d1 = __fdividef(1.f, 1.f + __expf(-(d1 + b1)));
                d2 = __fdividef(1.f, 1.f + __expf(-(d2 + b0)));
                d3 = __fdividef(1.f, 1.f + __expf(-(d3 + b1)));
            }
            *reinterpret_cast<float2*>(C + (size_t)r0 * Nout + cc)       = make_float2(d0, d1);
            *reinterpret_cast<float2*>(C + (size_t)(r0 + 8) * Nout + cc) = make_float2(d2, d3);
        }
    }
}

template<int EPI>
__global__ void __launch_bounds__(256, 2)
gemm_f16(const unsigned* __restrict__ Ah, const unsigned* __restrict__ Al,
         const unsigned* __restrict__ Wh,
         float* __restrict__ C, unsigned* __restrict__ Chi, unsigned* __restrict__ Clo,
         const float* __restrict__ bias, int Nout, int Kw)
{
    mma_gemm_core(Ah, Al, Wh, C, Chi, Clo, bias, EPI, Nout, Kw,
                  blockIdx.y * 128, blockIdx.x * 128);
}

struct ProjPtrs {
    const unsigned* Wh[4];
    float*          C[4];
};

// z: 0 = k (head-band normalize), 1 = v, 2 = q, 3 = beta (sigmoid+bias)
__global__ void __launch_bounds__(256, 2)
gemm_proj4(const unsigned* __restrict__ Ah, const unsigned* __restrict__ Al,
           ProjPtrs p, const float* __restrict__ bias, int Nout, int Kw)
{
    const int z = blockIdx.z;
    const int epi = (z == 0) ? 3 : ((z == 3) ? 2 : 0);
    mma_gemm_core(Ah, Al, p.Wh[z], p.C[z], nullptr, nullptr, bias,
                  epi, Nout, Kw, blockIdx.y * 128, blockIdx.x * 128);
}

// ---------------------------------------------------------------------------
// Barrier-free sequential scan (proven tiling: 2 cols/lane, 2 rows/warp,
// 16 warps/chain). Writes cell as fp16 hi/lo planes.
// ---------------------------------------------------------------------------
#define PF 4

__global__ void __launch_bounds__(128)
scan_kernel(const float* __restrict__ Kn, const float* __restrict__ Vp,
            const float* __restrict__ Qp, const float* __restrict__ Bp,
            unsigned short* __restrict__ cellh, unsigned short* __restrict__ celll,
            float* __restrict__ S_final, int writeS)
{
    const int g     = blockIdx.x * 4 + (threadIdx.x >> 5);
    const int chain = g >> 4;
    const int wc    = g & 15;
    const int l     = threadIdx.x & 31;
    const int i     = wc * 2 + (l >> 4);
    const int j0    = (l & 15) * 2;
    const size_t cb = ((size_t)(chain >> 3) * TT) * HN + (size_t)(chain & 7) * NN;

    float2 pk[PF], pq[PF];
    float  pv[PF], pb[PF];
#pragma unroll
    for (int d = 0; d < PF; ++d) {
        const size_t a = cb + (size_t)d * HN;
        pk[d] = *reinterpret_cast<const float2*>(Kn + a + j0);
        pq[d] = *reinterpret_cast<const float2*>(Qp + a + j0);
        pv[d] = Vp[a + i];
        pb[d] = Bp[a + i];
    }

    float S0 = 0.f, S1 = 0.f, sqp = 0.f;
    size_t base = cb;

    for (int t = 0; t < TT; t += PF) {
#pragma unroll
        for (int u = 0; u < PF; ++u) {
            const int tcur = t + u;
            const int tpre = (tcur + PF < TT) ? (tcur + PF) : (TT - 1);
            const size_t pa = cb + (size_t)tpre * HN;
            const float2 nk = *reinterpret_cast<const float2*>(Kn + pa + j0);
            const float2 nq = *reinterpret_cast<const float2*>(Qp + pa + j0);
            const float  nv = Vp[pa + i];
            const float  nb = Bp[pa + i];

            const float k0 = pk[u].x, k1 = pk[u].y;

            // on-chain reduction first (S·kn), then off-chain (prev S·q)
            float uu = fmaf(S1, k1, S0 * k0);
#pragma unroll
            for (int o = 1; o < 16; o <<= 1)
                uu += __shfl_xor_sync(0xffffffffu, uu, o);
            float sv = sqp;
#pragma unroll
            for (int o = 1; o < 16; o <<= 1)
                sv += __shfl_xor_sync(0xffffffffu, sv, o);

            if (tcur > 0 && (l & 15) == 0) {
                const float ov = sv * sv * __fdividef(1.f, 1.f + __expf(-sv));
                const unsigned short h = f2h(ov);
                cellh[base - HN + i] = h;
                celll[base - HN + i] = f2h(ov - h2f(h));
            }

            const float delta = pv[u] - uu;
            const float bi    = pb[u];
            const float z0 = fmaf(bi, S0, delta * k0);
            const float z1 = fmaf(bi, S1, delta * k1);
            const float e0 = __expf(2.f * z0);
            const float e1 = __expf(2.f * z1);
            S0 = 1.f - __fdividef(2.f, e0 + 1.f);
            S1 = 1.f - __fdividef(2.f, e1 + 1.f);

            sqp = fmaf(S1, pq[u].y, S0 * pq[u].x);

            pk[u] = nk; pq[u] = nq; pv[u] = nv; pb[u] = nb;
            base += HN;
        }
    }

    float sv = sqp;
#pragma unroll
    for (int o = 1; o < 16; o <<= 1) sv += __shfl_xor_sync(0xffffffffu, sv, o);
    if ((l & 15) == 0) {
        const float ov = sv * sv * __fdividef(1.f, 1.f + __expf(-sv));
        const unsigned short h = f2h(ov);
        cellh[base - HN + i] = h;
        celll[base - HN + i] = f2h(ov - h2f(h));
    }

    if (writeS) {
        S_final[((size_t)chain * NN + i) * NN + j0]     = S0;
        S_final[((size_t)chain * NN + i) * NN + j0 + 1] = S1;
    }
}

// ---------------------------------------------------------------------------
// Host launcher
// ---------------------------------------------------------------------------
extern "C" void kernel_launch(void* const* d_in, const int* in_sizes, int n_in,
                              void* d_out, int out_size)
{
    const float* x      = (const float*)d_in[0];
    const float* W_in   = (const float*)d_in[1];
    const float* W_k    = (const float*)d_in[2];
    const float* W_v    = (const float*)d_in[3];
    const float* W_q    = (const float*)d_in[4];
    const float* W_beta = (const float*)d_in[5];
    const float* b_beta = (const float*)d_in[6];
    const float* W_out  = (const float*)d_in[7];
    float* y = (float*)d_out;

    unsigned *xh, *xl, *xph, *xpl;
    unsigned *wih, *wkh, *wvh, *wqh, *wbh, *woh;
    float *k, *v, *q, *bt;
    unsigned short *cellh, *celll;
    cudaGetSymbolAddress((void**)&xh,  g_xh);  cudaGetSymbolAddress((void**)&xl,  g_xl);
    cudaGetSymbolAddress((void**)&xph, g_xph); cudaGetSymbolAddress((void**)&xpl, g_xpl);
    cudaGetSymbolAddress((void**)&wih, g_wih);
    cudaGetSymbolAddress((void**)&wkh, g_wkh);
    cudaGetSymbolAddress((void**)&wvh, g_wvh);
    cudaGetSymbolAddress((void**)&wqh, g_wqh);
    cudaGetSymbolAddress((void**)&wbh, g_wbh);
    cudaGetSymbolAddress((void**)&woh, g_woh);
    cudaGetSymbolAddress((void**)&k,  g_k);  cudaGetSymbolAddress((void**)&v,  g_v);
    cudaGetSymbolAddress((void**)&q,  g_q);  cudaGetSymbolAddress((void**)&bt, g_beta);
    cudaGetSymbolAddress((void**)&cellh, g_cellh);
    cudaGetSymbolAddress((void**)&celll, g_celll);

    cudaFuncSetAttribute(gemm_f16<0>, cudaFuncAttributeMaxDynamicSharedMemorySize, SMEM_GB);
    cudaFuncSetAttribute(gemm_f16<4>, cudaFuncAttributeMaxDynamicSharedMemorySize, SMEM_GB);
    cudaFuncSetAttribute(gemm_proj4,  cudaFuncAttributeMaxDynamicSharedMemorySize, SMEM_GB);

    const int M = MROWS;

    // 0. convert operands: x -> hi/lo fp16 planes; weights -> fp16 plane
    split_kernel<<<(M * DD / 2) / 256, 256>>>((const float2*)x, xh, xl, M * DD / 2);
    cvt_kernel<<<(DD * DD / 2) / 256, 256>>>((const float2*)W_in, wih, DD * DD / 2);
    cvt_kernel<<<(HN * DD / 2) / 256, 256>>>((const float2*)W_k, wkh, HN * DD / 2);
    cvt_kernel<<<(HN * DD / 2) / 256, 256>>>((const float2*)W_v, wvh, HN * DD / 2);
    cvt_kernel<<<(HN * DD / 2) / 256, 256>>>((const float2*)W_q, wqh, HN * DD / 2);
    cvt_kernel<<<(HN * DD / 2) / 256, 256>>>((const float2*)W_beta, wbh, HN * DD / 2);
    cvt_kernel<<<(DD * HN / 2) / 256, 256>>>((const float2*)W_out, woh, DD * HN / 2);

    // 1. xp = silu(x @ W_in^T) -> fp16 split planes (epi 4)
    gemm_f16<4><<<dim3(DD / 128, M / 128), 256, SMEM_GB>>>(
        xh, xl, wih, nullptr, xph, xpl, nullptr, DD, DD / 2);

    // 2. fused projections: k (normalized), v, q, beta
    ProjPtrs p;
    p.Wh[0] = wkh; p.C[0] = k;
    p.Wh[1] = wvh; p.C[1] = v;
    p.Wh[2] = wqh; p.C[2] = q;
    p.Wh[3] = wbh; p.C[3] = bt;
    gemm_proj4<<<dim3(HN / 128, M / 128, 4), 256, SMEM_GB>>>(
        xph, xpl, p, b_beta, HN, DD / 2);

    // 3. sequential scan (writes cell as fp16 split planes)
    const size_t y_elems = (size_t)M * DD;
    const int writeS = (out_size >= (int)(y_elems + (size_t)BB * HH * NN * NN)) ? 1 : 0;
    scan_kernel<<<256, 128>>>(k, v, q, bt, cellh, celll, y + y_elems, writeS);

    // 4. y = cell @ W_out^T
    gemm_f16<0><<<dim3(DD / 128, M / 128), 256, SMEM_GB>>>(
        (const unsigned*)cellh, (const unsigned*)celll, woh,
        y, nullptr, nullptr, nullptr, DD, HN / 2);
}

// round 17
// speedup vs baseline: 1.4143x; 1.0327x over previous
#include <cuda_runtime.h>
#include <cstddef>
#include <cstdint>

// Problem constants
#define BB 8
#define TT 2048
#define DD 1024
#define HH 8
#define NN 32
#define MROWS (BB*TT)          // 16384
#define HN (HH*NN)             // 256

// ---------------------------------------------------------------------------
// Scratch — __device__ globals. fp16 planes: packed f16 pairs along K.
// A-side (x, xp, cell): hi + lo planes. W-side: single rounded fp16 plane.
// ---------------------------------------------------------------------------
__device__ unsigned g_xh [(size_t)MROWS * DD / 2];
__device__ unsigned g_xl [(size_t)MROWS * DD / 2];
__device__ unsigned g_xph[(size_t)MROWS * DD / 2];
__device__ unsigned g_xpl[(size_t)MROWS * DD / 2];
__device__ unsigned g_wih[(size_t)DD * DD / 2];
__device__ unsigned g_wkh[(size_t)HN * DD / 2];
__device__ unsigned g_wvh[(size_t)HN * DD / 2];
__device__ unsigned g_wqh[(size_t)HN * DD / 2];
__device__ unsigned g_wbh[(size_t)HN * DD / 2];
__device__ unsigned g_woh[(size_t)DD * HN / 2];
__device__ float    g_k   [(size_t)MROWS * HN];
__device__ float    g_v   [(size_t)MROWS * HN];
__device__ float    g_q   [(size_t)MROWS * HN];
__device__ float    g_beta[(size_t)MROWS * HN];
__device__ unsigned short g_cellh[(size_t)MROWS * HN];
__device__ unsigned short g_celll[(size_t)MROWS * HN];

// ---------------------------------------------------------------------------
// fp16 helpers
// ---------------------------------------------------------------------------
__device__ __forceinline__ unsigned short f2h(float x) {
    unsigned short h;
    asm("cvt.rn.f16.f32 %0, %1;" : "=h"(h) : "f"(x));
    return h;
}
__device__ __forceinline__ float h2f(unsigned short h) {
    float r;
    asm("cvt.f32.f16 %0, %1;" : "=f"(r) : "h"(h));
    return r;
}
__device__ __forceinline__ float hi_f16(float x) { return h2f(f2h(x)); }
__device__ __forceinline__ unsigned pack_f16_pair(float e0, float e1) {
    unsigned d;
    asm("cvt.rn.f16x2.f32 %0, %1, %2;" : "=r"(d) : "f"(e1), "f"(e0));
    return d;
}

// ---------------------------------------------------------------------------
// Fused conversion kernel: 7 segments in one launch.
// Segment 0 (x) does hi/lo split; segments 1..6 (weights) do rounded cvt.
// ---------------------------------------------------------------------------
struct CvtJobs {
    const float2* src[7];
    unsigned*     hi [7];
    unsigned*     lo [7];   // nullptr for cvt-only
    int           end[7];   // cumulative word-pair counts
};

__global__ void __launch_bounds__(256)
cvt_all_kernel(CvtJobs jobs)
{
    const int idx = blockIdx.x * 256 + threadIdx.x;
    int start = 0;
#pragma unroll
    for (int s = 0; s < 7; ++s) {
        if (idx < jobs.end[s]) {
            const int li = idx - start;
            const float2 v = jobs.src[s][li];
            jobs.hi[s][li] = pack_f16_pair(v.x, v.y);
            if (jobs.lo[s])
                jobs.lo[s][li] = pack_f16_pair(v.x - hi_f16(v.x), v.y - hi_f16(v.y));
            return;
        }
        start = jobs.end[s];
    }
}

__device__ __forceinline__ void mma_f16(float d[4],
                                        unsigned a0, unsigned a1,
                                        unsigned a2, unsigned a3,
                                        unsigned b0, unsigned b1) {
    asm("mma.sync.aligned.m16n8k16.row.col.f32.f16.f16.f32 "
        "{%0,%1,%2,%3}, {%4,%5,%6,%7}, {%8,%9}, {%0,%1,%2,%3};"
        : "+f"(d[0]), "+f"(d[1]), "+f"(d[2]), "+f"(d[3])
        : "r"(a0), "r"(a1), "r"(a2), "r"(a3), "r"(b0), "r"(b1));
}

__device__ __forceinline__ void ldsm4(unsigned& r0, unsigned& r1,
                                      unsigned& r2, unsigned& r3, unsigned addr) {
    asm volatile("ldmatrix.sync.aligned.m8n8.x4.shared.b16 {%0,%1,%2,%3}, [%4];"
                 : "=r"(r0), "=r"(r1), "=r"(r2), "=r"(r3) : "r"(addr));
}

__device__ __forceinline__ void cpa16(unsigned dst, const void* src) {
    asm volatile("cp.async.cg.shared.global [%0], [%1], 16;" :: "r"(dst), "l"(src));
}
__device__ __forceinline__ void cpa_commit() {
    asm volatile("cp.async.commit_group;" ::: "memory");
}
template<int N>
__device__ __forceinline__ void cpa_wait() {
    asm volatile("cp.async.wait_group %0;" :: "n"(N) : "memory");
}

// ---------------------------------------------------------------------------
// fp16 2-term compensated tensor GEMM: C = epi( (A_hi + A_lo) @ W^T ).
// Block 128x128, chunk k16, 8 warps 2Mx4N (64x32 warp tile), 256 threads,
// 2 CTAs/SM, 4-stage cp.async ring (wait_group 2). 3 smem planes/stage.
// epi: 0 identity(f32), 2 sigmoid(acc+bias), 3 head-band row-norm,
//      4 silu + fp16-split-write
// ---------------------------------------------------------------------------
#define PLW 12
#define PLANE (128 * PLW)
#define STAGEW (3 * PLANE)
#define NSTAGE 4
#define SMEM_GB (NSTAGE * STAGEW * 4)   // 73728 bytes

__device__ __forceinline__ void mma_gemm_core(
    const unsigned* __restrict__ Ah, const unsigned* __restrict__ Al,
    const unsigned* __restrict__ Wh,
    float* __restrict__ C, unsigned* __restrict__ Chi, unsigned* __restrict__ Clo,
    const float* __restrict__ bias,
    int epi, int Nout, int Kw, int row0, int col0)
{
    extern __shared__ unsigned sm[];

    const int tid  = threadIdx.x;
    const int wid  = tid >> 5;
    const int lane = tid & 31;
    const int g    = lane >> 2;
    const int c    = lane & 3;
    const int wm   = (wid & 1) * 64;
    const int wn   = (wid >> 1) * 32;

    const int lr   = tid >> 1;
    const int wsel = tid & 1;
    const unsigned* Aph = Ah + (size_t)(row0 + lr) * Kw + wsel * 4;
    const unsigned* Apl = Al + (size_t)(row0 + lr) * Kw + wsel * 4;
    const unsigned* Wph = Wh + (size_t)(col0 + lr) * Kw + wsel * 4;
    const unsigned srow4 = (unsigned)(lr * PLW + wsel * 4) * 4;

    const unsigned smb = (unsigned)__cvta_generic_to_shared(&sm[0]);
    const unsigned aoff = (((lane & 15) * PLW) + ((lane >> 4) << 2)) * 4;
    const unsigned boff = ((((lane >> 4) * 8 + (lane & 7)) * PLW) + ((lane & 8) ? 4 : 0)) * 4;

    float acc[4][4][4];
#pragma unroll
    for (int mt = 0; mt < 4; ++mt)
#pragma unroll
        for (int nt = 0; nt < 4; ++nt)
#pragma unroll
            for (int e = 0; e < 4; ++e) acc[mt][nt][e] = 0.f;

    const int nchunks = Kw / 8;

    auto issue = [&](int chunk, int stage) {
        const int ko = chunk * 8;
        const unsigned sb = smb + (unsigned)stage * (STAGEW * 4);
        cpa16(sb + 0u * (PLANE * 4) + srow4, Aph + ko);
        cpa16(sb + 1u * (PLANE * 4) + srow4, Apl + ko);
        cpa16(sb + 2u * (PLANE * 4) + srow4, Wph + ko);
        cpa_commit();
    };

    issue(0, 0);
    issue(1, 1);
    issue(2, 2);

    int cur = 0;
    for (int chunk = 0; chunk < nchunks; ++chunk) {
        if (chunk + 3 <= nchunks)      cpa_wait<2>();
        else if (chunk + 2 == nchunks) cpa_wait<1>();
        else                           cpa_wait<0>();
        __syncthreads();

        const unsigned pb = smb + (unsigned)cur * (STAGEW * 4);

        unsigned bh[2][4];
#pragma unroll
        for (int pr = 0; pr < 2; ++pr) {
            const unsigned ba = pb + 2u * (PLANE * 4) + (unsigned)(wn + pr * 16) * PLW * 4 + boff;
            ldsm4(bh[pr][0], bh[pr][1], bh[pr][2], bh[pr][3], ba);
        }

#pragma unroll
        for (int mh = 0; mh < 2; ++mh) {
            unsigned ah[2][4], al[2][4];
#pragma unroll
            for (int m2 = 0; m2 < 2; ++m2) {
                const int rb = wm + (mh * 2 + m2) * 16;
                const unsigned aa = pb + (unsigned)rb * PLW * 4 + aoff;
                ldsm4(ah[m2][0], ah[m2][1], ah[m2][2], ah[m2][3], aa);
                ldsm4(al[m2][0], al[m2][1], al[m2][2], al[m2][3], aa + PLANE * 4);
            }
#pragma unroll
            for (int nt = 0; nt < 4; ++nt) {
                const unsigned b0 = bh[nt >> 1][(nt & 1) * 2];
                const unsigned b1 = bh[nt >> 1][(nt & 1) * 2 + 1];
#pragma unroll
                for (int m2 = 0; m2 < 2; ++m2) {
                    float* d = acc[mh * 2 + m2][nt];
                    mma_f16(d, ah[m2][0], ah[m2][1], ah[m2][2], ah[m2][3], b0, b1);
                    mma_f16(d, al[m2][0], al[m2][1], al[m2][2], al[m2][3], b0, b1);
                }
            }
        }

        if (chunk + 3 < nchunks) issue(chunk + 3, (cur + 3) & 3);
        cur = (cur + 1) & 3;
    }

    if (epi == 3) {
#pragma unroll
        for (int mt = 0; mt < 4; ++mt) {
            float se = 0.f, so = 0.f;
#pragma unroll
            for (int nt = 0; nt < 4; ++nt) {
                se = fmaf(acc[mt][nt][0], acc[mt][nt][0], se);
                se = fmaf(acc[mt][nt][1], acc[mt][nt][1], se);
                so = fmaf(acc[mt][nt][2], acc[mt][nt][2], so);
                so = fmaf(acc[mt][nt][3], acc[mt][nt][3], so);
            }
            se += __shfl_xor_sync(0xffffffffu, se, 1);
            se += __shfl_xor_sync(0xffffffffu, se, 2);
            so += __shfl_xor_sync(0xffffffffu, so, 1);
            so += __shfl_xor_sync(0xffffffffu, so, 2);
            const float ie = __fdividef(1.f, sqrtf(se) + 1e-6f);
            const float io = __fdividef(1.f, sqrtf(so) + 1e-6f);
            const int r0 = row0 + wm + mt * 16 + g;
#pragma unroll
            for (int nt = 0; nt < 4; ++nt) {
                const int cc = col0 + wn + nt * 8 + 2 * c;
                *reinterpret_cast<float2*>(C + (size_t)r0 * Nout + cc) =
                    make_float2(acc[mt][nt][0] * ie, acc[mt][nt][1] * ie);
                *reinterpret_cast<float2*>(C + (size_t)(r0 + 8) * Nout + cc) =
                    make_float2(acc[mt][nt][2] * io, acc[mt][nt][3] * io);
            }
        }
        return;
    }

#pragma unroll
    for (int mt = 0; mt < 4; ++mt) {
        const int r0 = row0 + wm + mt * 16 + g;
#pragma unroll
        for (int nt = 0; nt < 4; ++nt) {
            const int cc = col0 + wn + nt * 8 + 2 * c;
            float d0 = acc[mt][nt][0], d1 = acc[mt][nt][1];
            float d2 = acc[mt][nt][2], d3 = acc[mt][nt][3];
            if (epi == 4) {
                d0 = d0 * __fdividef(1.f, 1.f + __expf(-d0));
                d1 = d1 * __fdividef(1.f, 1.f + __expf(-d1));
                d2 = d2 * __fdividef(1.f, 1.f + __expf(-d2));
                d3 = d3 * __fdividef(1.f, 1.f + __expf(-d3));
                const size_t w0 = ((size_t)r0 * Nout + cc) >> 1;
                const size_t w1 = ((size_t)(r0 + 8) * Nout + cc) >> 1;
                Chi[w0] = pack_f16_pair(d0, d1);
                Clo[w0] = pack_f16_pair(d0 - hi_f16(d0), d1 - hi_f16(d1));
                Chi[w1] = pack_f16_pair(d2, d3);
                Clo[w1] = pack_f16_pair(d2 - hi_f16(d2), d3 - hi_f16(d3));
                continue;
            }
            if (epi == 2) {
                const float b0 = bias[cc], b1 = bias[cc + 1];
                d0 = __fdividef(1.f, 1.f + __expf(-(d0 + b0)));
                d1 = __fdividef(1.f, 1.f + __expf(-(d1 + b1)));
                d2 = __fdividef(1.f, 1.f + __expf(-(d2 + b0)));
                d3 = __fdividef(1.f, 1.f + __expf(-(d3 + b1)));
            }
            *reinterpret_cast<float2*>(C + (size_t)r0 * Nout + cc)       = make_float2(d0, d1);
            *reinterpret_cast<float2*>(C + (size_t)(r0 + 8) * Nout + cc) = make_float2(d2, d3);
        }
    }
}

template<int EPI>
__global__ void __launch_bounds__(256, 2)
gemm_f16(const unsigned* __restrict__ Ah, const unsigned* __restrict__ Al,
         const unsigned* __restrict__ Wh,
         float* __restrict__ C, unsigned* __restrict__ Chi, unsigned* __restrict__ Clo,
         const float* __restrict__ bias, int Nout, int Kw)
{
    mma_gemm_core(Ah, Al, Wh, C, Chi, Clo, bias, EPI, Nout, Kw,
                  blockIdx.y * 128, blockIdx.x * 128);
}

struct ProjPtrs {
    const unsigned* Wh[4];
    float*          C[4];
};

__global__ void __launch_bounds__(256, 2)
gemm_proj4(const unsigned* __restrict__ Ah, const unsigned* __restrict__ Al,
           ProjPtrs p, const float* __restrict__ bias, int Nout, int Kw)
{
    const int z = blockIdx.z;
    const int epi = (z == 0) ? 3 : ((z == 3) ? 2 : 0);
    mma_gemm_core(Ah, Al, p.Wh[z], p.C[z], nullptr, nullptr, bias,
                  epi, Nout, Kw, blockIdx.y * 128, blockIdx.x * 128);
}

// ---------------------------------------------------------------------------
// Barrier-free sequential scan, re-tiled: 4 cols/lane, 8-lane row groups,
// 4 rows/warp, 8 warps/chain (512 warps). Reduction = 2-level in-reg fma
// tree + 3 shfl levels (xor 1,2,4). Prefetch ring depth 8 (covers DRAM).
// Writes cell as fp16 hi/lo planes.
// ---------------------------------------------------------------------------
#define PF 8

__global__ void __launch_bounds__(128)
scan_kernel(const float* __restrict__ Kn, const float* __restrict__ Vp,
            const float* __restrict__ Qp, const float* __restrict__ Bp,
            unsigned short* __restrict__ cellh, unsigned short* __restrict__ celll,
            float* __restrict__ S_final, int writeS)
{
    const int w     = blockIdx.x * 4 + (threadIdx.x >> 5);  // 0..511
    const int chain = w >> 3;                 // 0..63
    const int wc    = w & 7;                  // warp-in-chain
    const int l     = threadIdx.x & 31;
    const int i     = wc * 4 + (l >> 3);      // state row 0..31
    const int j0    = (l & 7) * 4;            // first state col of lane
    const size_t cb = ((size_t)(chain >> 3) * TT) * HN + (size_t)(chain & 7) * NN;

    float4 pk[PF], pq[PF];
    float  pv[PF], pb[PF];
#pragma unroll
    for (int d = 0; d < PF; ++d) {
        const size_t a = cb + (size_t)d * HN;
        pk[d] = *reinterpret_cast<const float4*>(Kn + a + j0);
        pq[d] = *reinterpret_cast<const float4*>(Qp + a + j0);
        pv[d] = Vp[a + i];
        pb[d] = Bp[a + i];
    }

    float S0 = 0.f, S1 = 0.f, S2 = 0.f, S3 = 0.f, sqp = 0.f;
    size_t base = cb;

    for (int t = 0; t < TT; t += PF) {
#pragma unroll
        for (int u = 0; u < PF; ++u) {
            const int tcur = t + u;
            const int tpre = (tcur + PF < TT) ? (tcur + PF) : (TT - 1);
            const size_t pa = cb + (size_t)tpre * HN;
            const float4 nk = *reinterpret_cast<const float4*>(Kn + pa + j0);
            const float4 nq = *reinterpret_cast<const float4*>(Qp + pa + j0);
            const float  nv = Vp[pa + i];
            const float  nb = Bp[pa + i];

            const float k0 = pk[u].x, k1 = pk[u].y, k2 = pk[u].z, k3 = pk[u].w;

            // on-chain: retrieved_i = sum_j S_ij*kn_j (tree + 3 shfl levels)
            float uu = fmaf(S1, k1, S0 * k0) + fmaf(S3, k3, S2 * k2);
#pragma unroll
            for (int o = 1; o < 8; o <<= 1)
                uu += __shfl_xor_sync(0xffffffffu, uu, o);
            // off-chain: previous step's S·q
            float sv = sqp;
#pragma unroll
            for (int o = 1; o < 8; o <<= 1)
                sv += __shfl_xor_sync(0xffffffffu, sv, o);

            if (tcur > 0 && (l & 7) == 0) {
                const float ov = sv * sv * __fdividef(1.f, 1.f + __expf(-sv));
                const unsigned short h = f2h(ov);
                cellh[base - HN + i] = h;
                celll[base - HN + i] = f2h(ov - h2f(h));
            }

            const float delta = pv[u] - uu;
            const float bi    = pb[u];
            const float z0 = fmaf(bi, S0, delta * k0);
            const float z1 = fmaf(bi, S1, delta * k1);
            const float z2 = fmaf(bi, S2, delta * k2);
            const float z3 = fmaf(bi, S3, delta * k3);
            S0 = 1.f - __fdividef(2.f, __expf(2.f * z0) + 1.f);
            S1 = 1.f - __fdividef(2.f, __expf(2.f * z1) + 1.f);
            S2 = 1.f - __fdividef(2.f, __expf(2.f * z2) + 1.f);
            S3 = 1.f - __fdividef(2.f, __expf(2.f * z3) + 1.f);

            sqp = fmaf(S1, pq[u].y, S0 * pq[u].x) + fmaf(S3, pq[u].w, S2 * pq[u].z);

            pk[u] = nk; pq[u] = nq; pv[u] = nv; pb[u] = nb;
            base += HN;
        }
    }

    float sv = sqp;
#pragma unroll
    for (int o = 1; o < 8; o <<= 1) sv += __shfl_xor_sync(0xffffffffu, sv, o);
    if ((l & 7) == 0) {
        const float ov = sv * sv * __fdividef(1.f, 1.f + __expf(-sv));
        const unsigned short h = f2h(ov);
        cellh[base - HN + i] = h;
        celll[base - HN + i] = f2h(ov - h2f(h));
    }

    if (writeS) {
        float* dst = S_final + ((size_t)chain * NN + i) * NN + j0;
        dst[0] = S0; dst[1] = S1; dst[2] = S2; dst[3] = S3;
    }
}

// ---------------------------------------------------------------------------
// Host launcher
// ---------------------------------------------------------------------------
extern "C" void kernel_launch(void* const* d_in, const int* in_sizes, int n_in,
                              void* d_out, int out_size)
{
    const float* x      = (const float*)d_in[0];
    const float* W_in   = (const float*)d_in[1];
    const float* W_k    = (const float*)d_in[2];
    const float* W_v    = (const float*)d_in[3];
    const float* W_q    = (const float*)d_in[4];
    const float* W_beta = (const float*)d_in[5];
    const float* b_beta = (const float*)d_in[6];
    const float* W_out  = (const float*)d_in[7];
    float* y = (float*)d_out;

    unsigned *xh, *xl, *xph, *xpl;
    unsigned *wih, *wkh, *wvh, *wqh, *wbh, *woh;
    float *k, *v, *q, *bt;
    unsigned short *cellh, *celll;
    cudaGetSymbolAddress((void**)&xh,  g_xh);  cudaGetSymbolAddress((void**)&xl,  g_xl);
    cudaGetSymbolAddress((void**)&xph, g_xph); cudaGetSymbolAddress((void**)&xpl, g_xpl);
    cudaGetSymbolAddress((void**)&wih, g_wih);
    cudaGetSymbolAddress((void**)&wkh, g_wkh);
    cudaGetSymbolAddress((void**)&wvh, g_wvh);
    cudaGetSymbolAddress((void**)&wqh, g_wqh);
    cudaGetSymbolAddress((void**)&wbh, g_wbh);
    cudaGetSymbolAddress((void**)&woh, g_woh);
    cudaGetSymbolAddress((void**)&k,  g_k);  cudaGetSymbolAddress((void**)&v,  g_v);
    cudaGetSymbolAddress((void**)&q,  g_q);  cudaGetSymbolAddress((void**)&bt, g_beta);
    cudaGetSymbolAddress((void**)&cellh, g_cellh);
    cudaGetSymbolAddress((void**)&celll, g_celll);

    cudaFuncSetAttribute(gemm_f16<0>, cudaFuncAttributeMaxDynamicSharedMemorySize, SMEM_GB);
    cudaFuncSetAttribute(gemm_f16<4>, cudaFuncAttributeMaxDynamicSharedMemorySize, SMEM_GB);
    cudaFuncSetAttribute(gemm_proj4,  cudaFuncAttributeMaxDynamicSharedMemorySize, SMEM_GB);

    const int M = MROWS;

    // 0. fused conversions: x -> hi/lo fp16 planes; 6 weights -> fp16 planes
    CvtJobs jobs;
    const int nx  = M * DD / 2;          // 8388608
    const int nwi = DD * DD / 2;         // 524288
    const int nwp = HN * DD / 2;         // 131072
    jobs.src[0] = (const float2*)x;      jobs.hi[0] = xh;  jobs.lo[0] = xl;
    jobs.src[1] = (const float2*)W_in;   jobs.hi[1] = wih; jobs.lo[1] = nullptr;
    jobs.src[2] = (const float2*)W_k;    jobs.hi[2] = wkh; jobs.lo[2] = nullptr;
    jobs.src[3] = (const float2*)W_v;    jobs.hi[3] = wvh; jobs.lo[3] = nullptr;
    jobs.src[4] = (const float2*)W_q;    jobs.hi[4] = wqh; jobs.lo[4] = nullptr;
    jobs.src[5] = (const float2*)W_beta; jobs.hi[5] = wbh; jobs.lo[5] = nullptr;
    jobs.src[6] = (const float2*)W_out;  jobs.hi[6] = woh; jobs.lo[6] = nullptr;
    int acc = 0;
    const int seg[7] = {nx, nwi, nwp, nwp, nwp, nwp, nwp};
    for (int s = 0; s < 7; ++s) { acc += seg[s]; jobs.end[s] = acc; }
    cvt_all_kernel<<<(acc + 255) / 256, 256>>>(jobs);

    // 1. xp = silu(x @ W_in^T) -> fp16 split planes (epi 4)
    gemm_f16<4><<<dim3(DD / 128, M / 128), 256, SMEM_GB>>>(
        xh, xl, wih, nullptr, xph, xpl, nullptr, DD, DD / 2);

    // 2. fused projections: k (normalized), v, q, beta
    ProjPtrs p;
    p.Wh[0] = wkh; p.C[0] = k;
    p.Wh[1] = wvh; p.C[1] = v;
    p.Wh[2] = wqh; p.C[2] = q;
    p.Wh[3] = wbh; p.C[3] = bt;
    gemm_proj4<<<dim3(HN / 128, M / 128, 4), 256, SMEM_GB>>>(
        xph, xpl, p, b_beta, HN, DD / 2);

    // 3. sequential scan (8 warps/chain, 4 rows/warp, PF=8)
    const size_t y_elems = (size_t)M * DD;
    const int writeS = (out_size >= (int)(y_elems + (size_t)BB * HH * NN * NN)) ? 1 : 0;
    scan_kernel<<<128, 128>>>(k, v, q, bt, cellh, celll, y + y_elems, writeS);

    // 4. y = cell @ W_out^T
    gemm_f16<0><<<dim3(DD / 128, M / 128), 256, SMEM_GB>>>(
        (const unsigned*)cellh, (const unsigned*)celll, woh,
        y, nullptr, nullptr, nullptr, DD, HN / 2);
}